// round 10
// baseline (speedup 1.0000x reference)
#include <cuda_runtime.h>
#include <math.h>

#define BATCH 4
#define CH    1024
#define WID   2048
#define OC    512

// ---------------- scratch ----------------
__device__ float g_wpack[768 * 1024];
__device__ float g_proj[BATCH * 768 * WID];
__device__ float g_phir[BATCH * 128 * 512];
__device__ float g_gr[BATCH * 512 * 512];
__device__ float g_attn[(long)BATCH * WID * 512];
__device__ float g_ag[(long)BATCH * 512 * WID];
__device__ float g_x[(long)BATCH * CH * WID];
__device__ float g_h1[(long)BATCH * OC * WID];
__device__ float g_h2[(long)BATCH * OC * WID];
__device__ float g_gram[2][4 * 512 * 512];
__device__ float g_tr[16][4];
__device__ float g_sig[4];

// ---------------- pack theta|phi|g into [768,1024] ----------------
__global__ void k_pack(const float* __restrict__ wt, const float* __restrict__ wp,
                       const float* __restrict__ wg) {
    int i = blockIdx.x * 256 + threadIdx.x;
    if (i >= 768 * 1024) return;
    int r = i >> 10;
    g_wpack[i] = (r < 128) ? wt[i] : (r < 256) ? wp[i - 131072] : wg[i - 262144];
}

// ---------------- generic tiled GEMM 128x64, micro 8x4 ----------------
// AKM: A stored [K][M]; else [M][K].  BNK: B stored [N][K]; else [K][N].
// EPI: 0 none; 1 *1/(sig0*sig1); 2 *1/sig2; 3 C = 2*aux + (gma/sig3)*acc
template <int AKM, int BNK, int EPI>
__global__ void __launch_bounds__(256) k_gemm(
    const float* __restrict__ A, const float* __restrict__ B, float* __restrict__ C,
    int M, int N, int K, long sA, long sB, long sC,
    const float* __restrict__ aux, long sAux, const float* __restrict__ gma) {
    const int t = threadIdx.x;
    const int bz = blockIdx.z;
    A += (long)bz * sA;  B += (long)bz * sB;  C += (long)bz * sC;
    const int m0 = blockIdx.y * 128, n0 = blockIdx.x * 64;
    __shared__ float As[16][132];
    __shared__ float Bs[16][68];
    const int tm = t >> 4, tn = t & 15;
    float acc[8][4];
#pragma unroll
    for (int i = 0; i < 8; i++)
#pragma unroll
        for (int j = 0; j < 4; j++) acc[i][j] = 0.f;

    float4 ra0, ra1, rb0;
    const int nk = K >> 4;
    {   // prefetch chunk 0
        if (AKM) {
            int kk = t >> 5, mm = (t & 31) << 2;
            ra0 = *(const float4*)(A + (long)kk * M + m0 + mm);
            ra1 = *(const float4*)(A + (long)(kk + 8) * M + m0 + mm);
        } else {
            int mr = t >> 2, kv = (t & 3) << 2;
            ra0 = *(const float4*)(A + (long)(m0 + mr) * K + kv);
            ra1 = *(const float4*)(A + (long)(m0 + mr + 64) * K + kv);
        }
        if (!BNK) {
            int kk = t >> 4, nv = (t & 15) << 2;
            rb0 = *(const float4*)(B + (long)kk * N + n0 + nv);
        } else {
            int nr = t >> 2, kv = (t & 3) << 2;
            rb0 = *(const float4*)(B + (long)(n0 + nr) * K + kv);
        }
    }
    for (int kc = 0; kc < nk; kc++) {
        if (kc) __syncthreads();
        if (AKM) {
            int kk = t >> 5, mm = (t & 31) << 2;
            *(float4*)&As[kk][mm] = ra0;
            *(float4*)&As[kk + 8][mm] = ra1;
        } else {
            int mr = t >> 2, kv = (t & 3) << 2;
            As[kv + 0][mr] = ra0.x; As[kv + 1][mr] = ra0.y;
            As[kv + 2][mr] = ra0.z; As[kv + 3][mr] = ra0.w;
            As[kv + 0][mr + 64] = ra1.x; As[kv + 1][mr + 64] = ra1.y;
            As[kv + 2][mr + 64] = ra1.z; As[kv + 3][mr + 64] = ra1.w;
        }
        if (!BNK) {
            int kk = t >> 4, nv = (t & 15) << 2;
            *(float4*)&Bs[kk][nv] = rb0;
        } else {
            int nr = t >> 2, kv = (t & 3) << 2;
            Bs[kv + 0][nr] = rb0.x; Bs[kv + 1][nr] = rb0.y;
            Bs[kv + 2][nr] = rb0.z; Bs[kv + 3][nr] = rb0.w;
        }
        __syncthreads();
        if (kc + 1 < nk) {
            int k0 = (kc + 1) << 4;
            if (AKM) {
                int kk = t >> 5, mm = (t & 31) << 2;
                ra0 = *(const float4*)(A + (long)(k0 + kk) * M + m0 + mm);
                ra1 = *(const float4*)(A + (long)(k0 + kk + 8) * M + m0 + mm);
            } else {
                int mr = t >> 2, kv = (t & 3) << 2;
                ra0 = *(const float4*)(A + (long)(m0 + mr) * K + k0 + kv);
                ra1 = *(const float4*)(A + (long)(m0 + mr + 64) * K + k0 + kv);
            }
            if (!BNK) {
                int kk = t >> 4, nv = (t & 15) << 2;
                rb0 = *(const float4*)(B + (long)(k0 + kk) * N + n0 + nv);
            } else {
                int nr = t >> 2, kv = (t & 3) << 2;
                rb0 = *(const float4*)(B + (long)(n0 + nr) * K + k0 + kv);
            }
        }
#pragma unroll
        for (int kk = 0; kk < 16; kk++) {
            float a[8], bb[4];
            *(float4*)&a[0] = *(const float4*)&As[kk][tm << 3];
            *(float4*)&a[4] = *(const float4*)&As[kk][(tm << 3) + 4];
            *(float4*)&bb[0] = *(const float4*)&Bs[kk][tn << 2];
#pragma unroll
            for (int i = 0; i < 8; i++)
#pragma unroll
                for (int j = 0; j < 4; j++) acc[i][j] = fmaf(a[i], bb[j], acc[i][j]);
        }
    }
    float sc = 1.f, gm = 0.f;
    if (EPI == 1) sc = 1.f / (g_sig[0] * g_sig[1]);
    else if (EPI == 2) sc = 1.f / g_sig[2];
    else if (EPI == 3) gm = gma[0] / g_sig[3];
#pragma unroll
    for (int i = 0; i < 8; i++) {
        int m = m0 + (tm << 3) + i;
        long off = (long)m * N + n0 + (tn << 2);
        float4 v;
        if (EPI == 3) {
            float4 s4 = *(const float4*)(aux + (long)bz * sAux + off);
            v.x = 2.f * s4.x + gm * acc[i][0];
            v.y = 2.f * s4.y + gm * acc[i][1];
            v.z = 2.f * s4.z + gm * acc[i][2];
            v.w = 2.f * s4.w + gm * acc[i][3];
        } else {
            v.x = acc[i][0] * sc; v.y = acc[i][1] * sc;
            v.z = acc[i][2] * sc; v.w = acc[i][3] * sc;
        }
        *(float4*)(C + off) = v;
    }
}

// ---------------- trace-normalized squaring: C = (A/t)^2 ----------------
__global__ void __launch_bounds__(256) k_sq(int srcbuf, int step, int mpair) {
    const int j = (mpair ? 2 : 0) + blockIdx.z;
    const int m = mpair ? 512 : 128;
    const float* __restrict__ A = &g_gram[srcbuf][j * 262144];
    float* __restrict__ C = &g_gram[srcbuf ^ 1][j * 262144];
    const float inv = 1.0f / g_tr[step - 1][j];
    const int t = threadIdx.x;
    const int m0 = blockIdx.y * 128, n0 = blockIdx.x * 64;
    __shared__ float As[16][132];
    __shared__ float Bs[16][68];
    const int tm = t >> 4, tn = t & 15;
    float acc[8][4];
#pragma unroll
    for (int i = 0; i < 8; i++)
#pragma unroll
        for (int j2 = 0; j2 < 4; j2++) acc[i][j2] = 0.f;
    const int nk = m >> 4;
    const int mr = t >> 2, kv = (t & 3) << 2;
    const int kkb = t >> 4, nv = (t & 15) << 2;
    float4 ra0 = *(const float4*)(A + (long)(m0 + mr) * m + kv);
    float4 ra1 = *(const float4*)(A + (long)(m0 + mr + 64) * m + kv);
    float4 rb0 = *(const float4*)(A + (long)kkb * m + n0 + nv);
    for (int kc = 0; kc < nk; kc++) {
        if (kc) __syncthreads();
        As[kv + 0][mr] = ra0.x; As[kv + 1][mr] = ra0.y;
        As[kv + 2][mr] = ra0.z; As[kv + 3][mr] = ra0.w;
        As[kv + 0][mr + 64] = ra1.x; As[kv + 1][mr + 64] = ra1.y;
        As[kv + 2][mr + 64] = ra1.z; As[kv + 3][mr + 64] = ra1.w;
        *(float4*)&Bs[kkb][nv] = rb0;
        __syncthreads();
        if (kc + 1 < nk) {
            int k0 = (kc + 1) << 4;
            ra0 = *(const float4*)(A + (long)(m0 + mr) * m + k0 + kv);
            ra1 = *(const float4*)(A + (long)(m0 + mr + 64) * m + k0 + kv);
            rb0 = *(const float4*)(A + (long)(k0 + kkb) * m + n0 + nv);
        }
#pragma unroll
        for (int kk = 0; kk < 16; kk++) {
            float a[8], bb[4];
            *(float4*)&a[0] = *(const float4*)&As[kk][tm << 3];
            *(float4*)&a[4] = *(const float4*)&As[kk][(tm << 3) + 4];
            *(float4*)&bb[0] = *(const float4*)&Bs[kk][tn << 2];
#pragma unroll
            for (int i = 0; i < 8; i++)
#pragma unroll
                for (int j2 = 0; j2 < 4; j2++) acc[i][j2] = fmaf(a[i], bb[j2], acc[i][j2]);
        }
    }
    float s2 = inv * inv;
#pragma unroll
    for (int i = 0; i < 8; i++) {
        long off = (long)(m0 + (tm << 3) + i) * m + n0 + (tn << 2);
        float4 v;
        v.x = acc[i][0] * s2; v.y = acc[i][1] * s2;
        v.z = acc[i][2] * s2; v.w = acc[i][3] * s2;
        *(float4*)(C + off) = v;
    }
}

__global__ void k_trace(int step, int srcbuf) {
    int j = blockIdx.x;
    int m = (j < 2) ? 128 : 512;
    const float* A = &g_gram[srcbuf][j * 262144];
    __shared__ float red[512];
    float s = 0.f;
    for (int i = threadIdx.x; i < m; i += 512) s += A[(long)i * m + i];
    red[threadIdx.x] = s;
    __syncthreads();
    for (int o = 256; o > 0; o >>= 1) {
        if (threadIdx.x < o) red[threadIdx.x] += red[threadIdx.x + o];
        __syncthreads();
    }
    if (threadIdx.x == 0) g_tr[step][j] = red[0];
}

__global__ void k_sigfinal(int K) {
    int j = threadIdx.x;
    if (j >= 4) return;
    double la = 0.0, p = 1.0;
    for (int k = 0; k < K; k++) { la += log((double)g_tr[k][j]) * p; p *= 0.5; }
    la += log((double)g_tr[K][j]) * p;
    g_sig[j] = (float)exp(0.5 * la);
}

// ---------------- 2x2 maxpool over (c,w) + flat reshape ----------------
__global__ void k_pool(int which) {
    int C2 = which ? 256 : 64;
    int rowbase = which ? 256 : 128;
    float* out = which ? g_gr : g_phir;
    int total = BATCH * C2 * 1024;
    int i = blockIdx.x * 256 + threadIdx.x;
    if (i >= total) return;
    int w2 = i & 1023;
    int c2 = (i >> 10) % C2;
    int b = i / (C2 << 10);
    const float* P = &g_proj[((long)b * 768 + rowbase + 2 * c2) * WID + 2 * w2];
    float v = fmaxf(fmaxf(P[0], P[1]), fmaxf(P[WID], P[WID + 1]));
    out[(long)b * ((long)C2 << 10) + c2 * 1024 + w2] = v;
}

// ---------------- row softmax over 512 ----------------
__global__ void k_softmax() {
    int row = blockIdx.x * 8 + (threadIdx.x >> 5);
    int lane = threadIdx.x & 31;
    float* p = g_attn + (long)row * 512;
    float v[16];
#pragma unroll
    for (int r = 0; r < 4; r++)
        *(float4*)&v[r * 4] = *(const float4*)&p[r * 128 + lane * 4];
    float mx = v[0];
#pragma unroll
    for (int i = 1; i < 16; i++) mx = fmaxf(mx, v[i]);
#pragma unroll
    for (int o = 16; o > 0; o >>= 1) mx = fmaxf(mx, __shfl_xor_sync(0xffffffffu, mx, o));
    float s = 0.f;
#pragma unroll
    for (int i = 0; i < 16; i++) { v[i] = __expf(v[i] - mx); s += v[i]; }
#pragma unroll
    for (int o = 16; o > 0; o >>= 1) s += __shfl_xor_sync(0xffffffffu, s, o);
    float inv = 1.f / s;
#pragma unroll
    for (int i = 0; i < 16; i++) v[i] *= inv;
#pragma unroll
    for (int r = 0; r < 4; r++)
        *(float4*)&p[r * 128 + lane * 4] = *(const float4*)&v[r * 4];
}

// ---------------- conv1d k=3 'same' + bias + relu (+ residual) ----------------
template <int FINAL>
__global__ void __launch_bounds__(256) k_conv(
    const float* __restrict__ X, const float* __restrict__ Wc,
    const float* __restrict__ bias, float* __restrict__ Y,
    int IC, int OCout, const float* __restrict__ SRC) {
    const int b = blockIdx.z;
    X += (long)b * IC * WID;
    const int m0 = blockIdx.y * 64, n0 = blockIdx.x * 128;
    __shared__ float xs[16][132];   // cols 0..129 = w in [n0-1, n0+128]
    __shared__ float ws[16][196];   // [ic][m*3+k]
    const int t = threadIdx.x;
    const int tm = t >> 4, tn = t & 15;
    float acc[4][8];
#pragma unroll
    for (int i = 0; i < 4; i++)
#pragma unroll
        for (int j = 0; j < 8; j++) acc[i][j] = 0.f;
    float px[9], pw[12];
    const int nch = IC >> 4;
    // prefetch chunk 0
    {
        const int ic0 = 0;
#pragma unroll
        for (int i = 0; i < 9; i++) {
            int idx = t + i * 256;
            float v = 0.f;
            if (idx < 2080) {
                int row = idx / 130, col = idx - row * 130;
                int gw = n0 + col - 1;
                if (gw >= 0 && gw < WID) v = X[(long)(ic0 + row) * WID + gw];
            }
            px[i] = v;
        }
#pragma unroll
        for (int i = 0; i < 12; i++) {
            int idx = t + i * 256;
            int ii = idx / 192, rem = idx - ii * 192;
            int mloc = rem / 3, k = rem - mloc * 3;
            pw[i] = Wc[((long)(m0 + mloc) * IC + ic0 + ii) * 3 + k];
        }
    }
    for (int c = 0; c < nch; c++) {
        if (c) __syncthreads();
#pragma unroll
        for (int i = 0; i < 9; i++) {
            int idx = t + i * 256;
            if (idx < 2080) { int row = idx / 130; xs[row][idx - row * 130] = px[i]; }
        }
#pragma unroll
        for (int i = 0; i < 12; i++) {
            int idx = t + i * 256;
            int ii = idx / 192;
            ws[ii][idx - ii * 192] = pw[i];
        }
        __syncthreads();
        if (c + 1 < nch) {
            const int ic0 = (c + 1) << 4;
#pragma unroll
            for (int i = 0; i < 9; i++) {
                int idx = t + i * 256;
                float v = 0.f;
                if (idx < 2080) {
                    int row = idx / 130, col = idx - row * 130;
                    int gw = n0 + col - 1;
                    if (gw >= 0 && gw < WID) v = X[(long)(ic0 + row) * WID + gw];
                }
                px[i] = v;
            }
#pragma unroll
            for (int i = 0; i < 12; i++) {
                int idx = t + i * 256;
                int ii = idx / 192, rem = idx - ii * 192;
                int mloc = rem / 3, k = rem - mloc * 3;
                pw[i] = Wc[((long)(m0 + mloc) * IC + ic0 + ii) * 3 + k];
            }
        }
#pragma unroll
        for (int kk = 0; kk < 16; kk++) {
            float xv[10], wv[12];
            *(float4*)&xv[0] = *(const float4*)&xs[kk][tn << 3];
            *(float4*)&xv[4] = *(const float4*)&xs[kk][(tn << 3) + 4];
            xv[8] = xs[kk][(tn << 3) + 8];
            xv[9] = xs[kk][(tn << 3) + 9];
            *(float4*)&wv[0] = *(const float4*)&ws[kk][tm * 12];
            *(float4*)&wv[4] = *(const float4*)&ws[kk][tm * 12 + 4];
            *(float4*)&wv[8] = *(const float4*)&ws[kk][tm * 12 + 8];
#pragma unroll
            for (int i = 0; i < 4; i++)
#pragma unroll
                for (int j = 0; j < 8; j++) {
                    acc[i][j] = fmaf(wv[i * 3 + 0], xv[j + 0], acc[i][j]);
                    acc[i][j] = fmaf(wv[i * 3 + 1], xv[j + 1], acc[i][j]);
                    acc[i][j] = fmaf(wv[i * 3 + 2], xv[j + 2], acc[i][j]);
                }
        }
    }
#pragma unroll
    for (int i = 0; i < 4; i++) {
        int m = m0 + (tm << 2) + i;
        float bb = bias[m];
        long off = ((long)b * OCout + m) * WID + n0 + (tn << 3);
        float4 v0, v1;
        v0.x = fmaxf(acc[i][0] + bb, 0.f); v0.y = fmaxf(acc[i][1] + bb, 0.f);
        v0.z = fmaxf(acc[i][2] + bb, 0.f); v0.w = fmaxf(acc[i][3] + bb, 0.f);
        v1.x = fmaxf(acc[i][4] + bb, 0.f); v1.y = fmaxf(acc[i][5] + bb, 0.f);
        v1.z = fmaxf(acc[i][6] + bb, 0.f); v1.w = fmaxf(acc[i][7] + bb, 0.f);
        if (FINAL) {
            long soff = ((long)b * CH + m) * WID + n0 + (tn << 3);
            float4 s0 = *(const float4*)(SRC + soff);
            float4 s1 = *(const float4*)(SRC + soff + 4);
            v0.x += s0.x; v0.y += s0.y; v0.z += s0.z; v0.w += s0.w;
            v1.x += s1.x; v1.y += s1.y; v1.z += s1.z; v1.w += s1.w;
        }
        *(float4*)(Y + off) = v0;
        *(float4*)(Y + off + 4) = v1;
    }
}

// ---------------- launch ----------------
extern "C" void kernel_launch(void* const* d_in, const int* in_sizes, int n_in,
                              void* d_out, int out_size) {
    const float* src     = (const float*)d_in[0];
    const float* w_theta = (const float*)d_in[1];
    const float* w_phi   = (const float*)d_in[2];
    const float* w_g     = (const float*)d_in[3];
    const float* w_o     = (const float*)d_in[4];
    const float* gamma   = (const float*)d_in[5];
    const float* w_c1 = (const float*)d_in[6];  const float* b_c1 = (const float*)d_in[7];
    const float* w_c2 = (const float*)d_in[8];  const float* b_c2 = (const float*)d_in[9];
    const float* w_c3 = (const float*)d_in[10]; const float* b_c3 = (const float*)d_in[11];
    const float* w_c4 = (const float*)d_in[12]; const float* b_c4 = (const float*)d_in[13];
    float* out = (float*)d_out;

    static float *p_wpack = nullptr, *p_proj, *p_phir, *p_gr, *p_attn, *p_ag,
                 *p_x, *p_h1, *p_h2, *p_gram;
    if (!p_wpack) {
        cudaGetSymbolAddress((void**)&p_wpack, g_wpack);
        cudaGetSymbolAddress((void**)&p_proj,  g_proj);
        cudaGetSymbolAddress((void**)&p_phir,  g_phir);
        cudaGetSymbolAddress((void**)&p_gr,    g_gr);
        cudaGetSymbolAddress((void**)&p_attn,  g_attn);
        cudaGetSymbolAddress((void**)&p_ag,    g_ag);
        cudaGetSymbolAddress((void**)&p_x,     g_x);
        cudaGetSymbolAddress((void**)&p_h1,    g_h1);
        cudaGetSymbolAddress((void**)&p_h2,    g_h2);
        cudaGetSymbolAddress((void**)&p_gram,  g_gram);
    }

    // 1) pack projection weights, run projections [768,2048] per batch
    k_pack<<<3072, 256>>>(w_theta, w_phi, w_g);
    k_gemm<0, 0, 0><<<dim3(32, 6, 4), 256>>>(p_wpack, src, p_proj,
        768, 2048, 1024, 0, 2097152, 1572864, nullptr, 0, nullptr);
    // 2) pools (flat reshape is free)
    k_pool<<<1024, 256>>>(0);
    k_pool<<<4096, 256>>>(1);
    // 3) Gram matrices via the same GEMM
    k_gemm<0, 1, 0><<<dim3(2, 1, 1), 256>>>(w_theta, w_theta, p_gram,
        128, 128, 1024, 0, 0, 0, nullptr, 0, nullptr);
    k_gemm<0, 1, 0><<<dim3(2, 1, 1), 256>>>(w_phi, w_phi, p_gram + 262144,
        128, 128, 1024, 0, 0, 0, nullptr, 0, nullptr);
    k_gemm<0, 1, 0><<<dim3(8, 4, 1), 256>>>(w_g, w_g, p_gram + 524288,
        512, 512, 1024, 0, 0, 0, nullptr, 0, nullptr);
    k_gemm<1, 0, 0><<<dim3(8, 4, 1), 256>>>(w_o, w_o, p_gram + 786432,
        512, 512, 1024, 0, 0, 0, nullptr, 0, nullptr);
    // 4) trace-power chain for spectral norms
    k_trace<<<4, 512>>>(0, 0);
    for (int s = 1; s <= 12; s++) {
        k_sq<<<dim3(2, 1, 2), 256>>>((s - 1) & 1, s, 0);
        k_sq<<<dim3(8, 4, 2), 256>>>((s - 1) & 1, s, 1);
        k_trace<<<4, 512>>>(s, s & 1);
    }
    k_sigfinal<<<1, 4>>>(12);
    // 5) logits = theta^T @ phi_r, scaled 1/(sig_t*sig_p), then softmax
    k_gemm<1, 0, 1><<<dim3(8, 16, 4), 256>>>(p_proj, p_phir, p_attn,
        2048, 512, 128, 1572864, 65536, 1048576, nullptr, 0, nullptr);
    k_softmax<<<1024, 256>>>();
    // 6) attn_g = g_r @ attn^T, scaled 1/sig_g
    k_gemm<0, 1, 2><<<dim3(32, 4, 4), 256>>>(p_gr, p_attn, p_ag,
        512, 2048, 512, 262144, 1048576, 1048576, nullptr, 0, nullptr);
    // 7) x = 2*src + (gamma/sig_o) * (w_o @ attn_g)
    k_gemm<0, 0, 3><<<dim3(32, 8, 4), 256>>>(w_o, p_ag, p_x,
        1024, 2048, 512, 0, 1048576, 2097152, src, 2097152, gamma);
    // 8) conv FFN
    k_conv<0><<<dim3(16, 8, 4), 256>>>(p_x,  w_c1, b_c1, p_h1, 1024, 512, nullptr);
    k_conv<0><<<dim3(16, 8, 4), 256>>>(p_h1, w_c2, b_c2, p_h2, 512, 512, nullptr);
    k_conv<0><<<dim3(16, 8, 4), 256>>>(p_h2, w_c3, b_c3, p_h1, 512, 512, nullptr);
    k_conv<1><<<dim3(16, 16, 4), 256>>>(p_h1, w_c4, b_c4, out, 512, 1024, src);
    (void)in_sizes; (void)n_in; (void)out_size;
}

// round 11
// speedup vs baseline: 1.0723x; 1.0723x over previous
#include <cuda_runtime.h>
#include <math.h>

#define BATCH 4
#define CH    1024
#define WID   2048
#define OC    512

typedef unsigned long long u64;

__device__ __forceinline__ u64 dup2(float v) {
    u64 r; asm("mov.b64 %0,{%1,%1};" : "=l"(r) : "f"(v)); return r;
}
__device__ __forceinline__ void fma2(u64& c, u64 a, u64 b) {
    asm("fma.rn.f32x2 %0,%1,%2,%0;" : "+l"(c) : "l"(a), "l"(b));
}
__device__ __forceinline__ float2 up2(u64 v) {
    float2 f; asm("mov.b64 {%0,%1},%2;" : "=f"(f.x), "=f"(f.y) : "l"(v)); return f;
}

// ---------------- scratch ----------------
__device__ float g_wpack[768 * 1024];
__device__ float g_proj[BATCH * 768 * WID];
__device__ float g_phir[BATCH * 128 * 512];
__device__ float g_gr[BATCH * 512 * 512];
__device__ float g_attn[(long)BATCH * WID * 512];
__device__ float g_ag[(long)BATCH * 512 * WID];
__device__ float g_x[(long)BATCH * CH * WID];
__device__ float g_h1[(long)BATCH * OC * WID];
__device__ float g_h2[(long)BATCH * OC * WID];
__device__ float g_gram[2][4 * 512 * 512];
__device__ float g_tr[16][4];
__device__ float g_sig[4];

// ---------------- pack theta|phi|g into [768,1024] ----------------
__global__ void k_pack(const float* __restrict__ wt, const float* __restrict__ wp,
                       const float* __restrict__ wg) {
    int i = blockIdx.x * 256 + threadIdx.x;
    if (i >= 768 * 1024) return;
    int r = i >> 10;
    g_wpack[i] = (r < 128) ? wt[i] : (r < 256) ? wp[i - 131072] : wg[i - 262144];
}

// ---------------- generic tiled GEMM 128x64, micro 8x4, f32x2 packed ----------
// AKM: A stored [K][M]; else [M][K].  BNK: B stored [N][K]; else [K][N].
// EPI: 0 none; 1 *1/(sig0*sig1); 2 *1/sig2; 3 C = 2*aux + (gma/sig3)*acc
template <int AKM, int BNK, int EPI>
__global__ void __launch_bounds__(256) k_gemm(
    const float* __restrict__ A, const float* __restrict__ B, float* __restrict__ C,
    int M, int N, int K, long sA, long sB, long sC,
    const float* __restrict__ aux, long sAux, const float* __restrict__ gma) {
    const int t = threadIdx.x;
    const int bz = blockIdx.z;
    A += (long)bz * sA;  B += (long)bz * sB;  C += (long)bz * sC;
    const int m0 = blockIdx.y * 128, n0 = blockIdx.x * 64;
    __shared__ float As[16][132];
    __shared__ float Bs[16][68];
    const int tm = t >> 4, tn = t & 15;
    u64 acc[4][4];  // [m-pair][n]
#pragma unroll
    for (int i = 0; i < 4; i++)
#pragma unroll
        for (int j = 0; j < 4; j++) acc[i][j] = 0ull;

    float4 ra0, ra1, rb0;
    const int nk = K >> 4;
    {   // prefetch chunk 0
        if (AKM) {
            int kk = t >> 5, mm = (t & 31) << 2;
            ra0 = *(const float4*)(A + (long)kk * M + m0 + mm);
            ra1 = *(const float4*)(A + (long)(kk + 8) * M + m0 + mm);
        } else {
            int mr = t >> 2, kv = (t & 3) << 2;
            ra0 = *(const float4*)(A + (long)(m0 + mr) * K + kv);
            ra1 = *(const float4*)(A + (long)(m0 + mr + 64) * K + kv);
        }
        if (!BNK) {
            int kk = t >> 4, nv = (t & 15) << 2;
            rb0 = *(const float4*)(B + (long)kk * N + n0 + nv);
        } else {
            int nr = t >> 2, kv = (t & 3) << 2;
            rb0 = *(const float4*)(B + (long)(n0 + nr) * K + kv);
        }
    }
    for (int kc = 0; kc < nk; kc++) {
        if (kc) __syncthreads();
        if (AKM) {
            int kk = t >> 5, mm = (t & 31) << 2;
            *(float4*)&As[kk][mm] = ra0;
            *(float4*)&As[kk + 8][mm] = ra1;
        } else {
            int mr = t >> 2, kv = (t & 3) << 2;
            As[kv + 0][mr] = ra0.x; As[kv + 1][mr] = ra0.y;
            As[kv + 2][mr] = ra0.z; As[kv + 3][mr] = ra0.w;
            As[kv + 0][mr + 64] = ra1.x; As[kv + 1][mr + 64] = ra1.y;
            As[kv + 2][mr + 64] = ra1.z; As[kv + 3][mr + 64] = ra1.w;
        }
        if (!BNK) {
            int kk = t >> 4, nv = (t & 15) << 2;
            *(float4*)&Bs[kk][nv] = rb0;
        } else {
            int nr = t >> 2, kv = (t & 3) << 2;
            Bs[kv + 0][nr] = rb0.x; Bs[kv + 1][nr] = rb0.y;
            Bs[kv + 2][nr] = rb0.z; Bs[kv + 3][nr] = rb0.w;
        }
        __syncthreads();
        if (kc + 1 < nk) {
            int k0 = (kc + 1) << 4;
            if (AKM) {
                int kk = t >> 5, mm = (t & 31) << 2;
                ra0 = *(const float4*)(A + (long)(k0 + kk) * M + m0 + mm);
                ra1 = *(const float4*)(A + (long)(k0 + kk + 8) * M + m0 + mm);
            } else {
                int mr = t >> 2, kv = (t & 3) << 2;
                ra0 = *(const float4*)(A + (long)(m0 + mr) * K + k0 + kv);
                ra1 = *(const float4*)(A + (long)(m0 + mr + 64) * K + k0 + kv);
            }
            if (!BNK) {
                int kk = t >> 4, nv = (t & 15) << 2;
                rb0 = *(const float4*)(B + (long)(k0 + kk) * N + n0 + nv);
            } else {
                int nr = t >> 2, kv = (t & 3) << 2;
                rb0 = *(const float4*)(B + (long)(n0 + nr) * K + k0 + kv);
            }
        }
#pragma unroll
        for (int kk = 0; kk < 16; kk++) {
            const ulonglong2 a01 = *(const ulonglong2*)&As[kk][tm << 3];
            const ulonglong2 a23 = *(const ulonglong2*)&As[kk][(tm << 3) + 4];
            const float4 bv = *(const float4*)&Bs[kk][tn << 2];
            u64 b0 = dup2(bv.x), b1 = dup2(bv.y), b2 = dup2(bv.z), b3 = dup2(bv.w);
            fma2(acc[0][0], a01.x, b0); fma2(acc[0][1], a01.x, b1);
            fma2(acc[0][2], a01.x, b2); fma2(acc[0][3], a01.x, b3);
            fma2(acc[1][0], a01.y, b0); fma2(acc[1][1], a01.y, b1);
            fma2(acc[1][2], a01.y, b2); fma2(acc[1][3], a01.y, b3);
            fma2(acc[2][0], a23.x, b0); fma2(acc[2][1], a23.x, b1);
            fma2(acc[2][2], a23.x, b2); fma2(acc[2][3], a23.x, b3);
            fma2(acc[3][0], a23.y, b0); fma2(acc[3][1], a23.y, b1);
            fma2(acc[3][2], a23.y, b2); fma2(acc[3][3], a23.y, b3);
        }
    }
    float sc = 1.f, gm = 0.f;
    if (EPI == 1) sc = 1.f / (g_sig[0] * g_sig[1]);
    else if (EPI == 2) sc = 1.f / g_sig[2];
    else if (EPI == 3) gm = gma[0] / g_sig[3];
#pragma unroll
    for (int p = 0; p < 4; p++) {
        float va[4], vb[4];
#pragma unroll
        for (int j = 0; j < 4; j++) {
            float2 u = up2(acc[p][j]);
            va[j] = u.x; vb[j] = u.y;
        }
#pragma unroll
        for (int h = 0; h < 2; h++) {
            const float* r = h ? vb : va;
            int m = m0 + (tm << 3) + 2 * p + h;
            long off = (long)m * N + n0 + (tn << 2);
            float4 v;
            if (EPI == 3) {
                float4 s4 = *(const float4*)(aux + (long)bz * sAux + off);
                v.x = 2.f * s4.x + gm * r[0];
                v.y = 2.f * s4.y + gm * r[1];
                v.z = 2.f * s4.z + gm * r[2];
                v.w = 2.f * s4.w + gm * r[3];
            } else {
                v.x = r[0] * sc; v.y = r[1] * sc;
                v.z = r[2] * sc; v.w = r[3] * sc;
            }
            *(float4*)(C + off) = v;
        }
    }
}

// ---------------- trace-normalized squaring: C = (A/t)^2, f32x2 packed -------
__global__ void __launch_bounds__(256) k_sq(int srcbuf, int step, int mpair) {
    const int j = (mpair ? 2 : 0) + blockIdx.z;
    const int m = mpair ? 512 : 128;
    const float* __restrict__ A = &g_gram[srcbuf][j * 262144];
    float* __restrict__ C = &g_gram[srcbuf ^ 1][j * 262144];
    const float inv = 1.0f / g_tr[step - 1][j];
    const int t = threadIdx.x;
    const int m0 = blockIdx.y * 128, n0 = blockIdx.x * 64;
    __shared__ float As[16][132];
    __shared__ float Bs[16][68];
    const int tm = t >> 4, tn = t & 15;
    u64 acc[4][4];
#pragma unroll
    for (int i = 0; i < 4; i++)
#pragma unroll
        for (int j2 = 0; j2 < 4; j2++) acc[i][j2] = 0ull;
    const int nk = m >> 4;
    const int mr = t >> 2, kv = (t & 3) << 2;
    const int kkb = t >> 4, nv = (t & 15) << 2;
    float4 ra0 = *(const float4*)(A + (long)(m0 + mr) * m + kv);
    float4 ra1 = *(const float4*)(A + (long)(m0 + mr + 64) * m + kv);
    float4 rb0 = *(const float4*)(A + (long)kkb * m + n0 + nv);
    for (int kc = 0; kc < nk; kc++) {
        if (kc) __syncthreads();
        As[kv + 0][mr] = ra0.x; As[kv + 1][mr] = ra0.y;
        As[kv + 2][mr] = ra0.z; As[kv + 3][mr] = ra0.w;
        As[kv + 0][mr + 64] = ra1.x; As[kv + 1][mr + 64] = ra1.y;
        As[kv + 2][mr + 64] = ra1.z; As[kv + 3][mr + 64] = ra1.w;
        *(float4*)&Bs[kkb][nv] = rb0;
        __syncthreads();
        if (kc + 1 < nk) {
            int k0 = (kc + 1) << 4;
            ra0 = *(const float4*)(A + (long)(m0 + mr) * m + k0 + kv);
            ra1 = *(const float4*)(A + (long)(m0 + mr + 64) * m + k0 + kv);
            rb0 = *(const float4*)(A + (long)(k0 + kkb) * m + n0 + nv);
        }
#pragma unroll
        for (int kk = 0; kk < 16; kk++) {
            const ulonglong2 a01 = *(const ulonglong2*)&As[kk][tm << 3];
            const ulonglong2 a23 = *(const ulonglong2*)&As[kk][(tm << 3) + 4];
            const float4 bv = *(const float4*)&Bs[kk][tn << 2];
            u64 b0 = dup2(bv.x), b1 = dup2(bv.y), b2 = dup2(bv.z), b3 = dup2(bv.w);
            fma2(acc[0][0], a01.x, b0); fma2(acc[0][1], a01.x, b1);
            fma2(acc[0][2], a01.x, b2); fma2(acc[0][3], a01.x, b3);
            fma2(acc[1][0], a01.y, b0); fma2(acc[1][1], a01.y, b1);
            fma2(acc[1][2], a01.y, b2); fma2(acc[1][3], a01.y, b3);
            fma2(acc[2][0], a23.x, b0); fma2(acc[2][1], a23.x, b1);
            fma2(acc[2][2], a23.x, b2); fma2(acc[2][3], a23.x, b3);
            fma2(acc[3][0], a23.y, b0); fma2(acc[3][1], a23.y, b1);
            fma2(acc[3][2], a23.y, b2); fma2(acc[3][3], a23.y, b3);
        }
    }
    float s2 = inv * inv;
#pragma unroll
    for (int p = 0; p < 4; p++) {
        float2 u0 = up2(acc[p][0]), u1 = up2(acc[p][1]),
               u2 = up2(acc[p][2]), u3 = up2(acc[p][3]);
        long offA = (long)(m0 + (tm << 3) + 2 * p) * m + n0 + (tn << 2);
        float4 v;
        v.x = u0.x * s2; v.y = u1.x * s2; v.z = u2.x * s2; v.w = u3.x * s2;
        *(float4*)(C + offA) = v;
        v.x = u0.y * s2; v.y = u1.y * s2; v.z = u2.y * s2; v.w = u3.y * s2;
        *(float4*)(C + offA + m) = v;
    }
}

__global__ void k_trace(int step, int srcbuf) {
    int j = blockIdx.x;
    int m = (j < 2) ? 128 : 512;
    const float* A = &g_gram[srcbuf][j * 262144];
    __shared__ float red[512];
    float s = 0.f;
    for (int i = threadIdx.x; i < m; i += 512) s += A[(long)i * m + i];
    red[threadIdx.x] = s;
    __syncthreads();
    for (int o = 256; o > 0; o >>= 1) {
        if (threadIdx.x < o) red[threadIdx.x] += red[threadIdx.x + o];
        __syncthreads();
    }
    if (threadIdx.x == 0) g_tr[step][j] = red[0];
}

__global__ void k_sigfinal(int K) {
    int j = threadIdx.x;
    if (j >= 4) return;
    double la = 0.0, p = 1.0;
    for (int k = 0; k < K; k++) { la += log((double)g_tr[k][j]) * p; p *= 0.5; }
    la += log((double)g_tr[K][j]) * p;
    g_sig[j] = (float)exp(0.5 * la);
}

// ---------------- 2x2 maxpool over (c,w) + flat reshape ----------------
__global__ void k_pool(int which) {
    int C2 = which ? 256 : 64;
    int rowbase = which ? 256 : 128;
    float* out = which ? g_gr : g_phir;
    int total = BATCH * C2 * 1024;
    int i = blockIdx.x * 256 + threadIdx.x;
    if (i >= total) return;
    int w2 = i & 1023;
    int c2 = (i >> 10) % C2;
    int b = i / (C2 << 10);
    const float* P = &g_proj[((long)b * 768 + rowbase + 2 * c2) * WID + 2 * w2];
    float v = fmaxf(fmaxf(P[0], P[1]), fmaxf(P[WID], P[WID + 1]));
    out[(long)b * ((long)C2 << 10) + c2 * 1024 + w2] = v;
}

// ---------------- row softmax over 512 ----------------
__global__ void k_softmax() {
    int row = blockIdx.x * 8 + (threadIdx.x >> 5);
    int lane = threadIdx.x & 31;
    float* p = g_attn + (long)row * 512;
    float v[16];
#pragma unroll
    for (int r = 0; r < 4; r++)
        *(float4*)&v[r * 4] = *(const float4*)&p[r * 128 + lane * 4];
    float mx = v[0];
#pragma unroll
    for (int i = 1; i < 16; i++) mx = fmaxf(mx, v[i]);
#pragma unroll
    for (int o = 16; o > 0; o >>= 1) mx = fmaxf(mx, __shfl_xor_sync(0xffffffffu, mx, o));
    float s = 0.f;
#pragma unroll
    for (int i = 0; i < 16; i++) { v[i] = __expf(v[i] - mx); s += v[i]; }
#pragma unroll
    for (int o = 16; o > 0; o >>= 1) s += __shfl_xor_sync(0xffffffffu, s, o);
    float inv = 1.f / s;
#pragma unroll
    for (int i = 0; i < 16; i++) v[i] *= inv;
#pragma unroll
    for (int r = 0; r < 4; r++)
        *(float4*)&p[r * 128 + lane * 4] = *(const float4*)&v[r * 4];
}

// -------- conv1d k=3 'same' + bias + relu (+ residual), f32x2 packed ---------
template <int FINAL>
__global__ void __launch_bounds__(256) k_conv(
    const float* __restrict__ X, const float* __restrict__ Wc,
    const float* __restrict__ bias, float* __restrict__ Y,
    int IC, int OCout, const float* __restrict__ SRC) {
    const int b = blockIdx.z;
    X += (long)b * IC * WID;
    const int m0 = blockIdx.y * 64, n0 = blockIdx.x * 128;
    __shared__ float xs[16][132];   // cols 0..129 = w in [n0-1, n0+128]
    __shared__ float ws[16][204];   // [ic][k*68 + m]  (k-major for oc-pair LDS)
    const int t = threadIdx.x;
    const int tm = t >> 4, tn = t & 15;
    u64 accP[2][8];  // [oc-pair][w]; lo = oc even of pair
#pragma unroll
    for (int i = 0; i < 2; i++)
#pragma unroll
        for (int j = 0; j < 8; j++) accP[i][j] = 0ull;
    float px[9], pw[12];
    const int nch = IC >> 4;
    // prefetch chunk 0
    {
        const int ic0 = 0;
#pragma unroll
        for (int i = 0; i < 9; i++) {
            int idx = t + i * 256;
            float v = 0.f;
            if (idx < 2080) {
                int row = idx / 130, col = idx - row * 130;
                int gw = n0 + col - 1;
                if (gw >= 0 && gw < WID) v = X[(long)(ic0 + row) * WID + gw];
            }
            px[i] = v;
        }
#pragma unroll
        for (int i = 0; i < 12; i++) {
            int idx = t + i * 256;
            int ii = idx / 192, rem = idx - ii * 192;
            int mloc = rem / 3, k = rem - mloc * 3;
            pw[i] = Wc[((long)(m0 + mloc) * IC + ic0 + ii) * 3 + k];
        }
    }
    for (int c = 0; c < nch; c++) {
        if (c) __syncthreads();
#pragma unroll
        for (int i = 0; i < 9; i++) {
            int idx = t + i * 256;
            if (idx < 2080) { int row = idx / 130; xs[row][idx - row * 130] = px[i]; }
        }
#pragma unroll
        for (int i = 0; i < 12; i++) {
            int idx = t + i * 256;
            int ii = idx / 192, rem = idx - ii * 192;
            int mloc = rem / 3, k = rem - mloc * 3;
            ws[ii][k * 68 + mloc] = pw[i];
        }
        __syncthreads();
        if (c + 1 < nch) {
            const int ic0 = (c + 1) << 4;
#pragma unroll
            for (int i = 0; i < 9; i++) {
                int idx = t + i * 256;
                float v = 0.f;
                if (idx < 2080) {
                    int row = idx / 130, col = idx - row * 130;
                    int gw = n0 + col - 1;
                    if (gw >= 0 && gw < WID) v = X[(long)(ic0 + row) * WID + gw];
                }
                px[i] = v;
            }
#pragma unroll
            for (int i = 0; i < 12; i++) {
                int idx = t + i * 256;
                int ii = idx / 192, rem = idx - ii * 192;
                int mloc = rem / 3, k = rem - mloc * 3;
                pw[i] = Wc[((long)(m0 + mloc) * IC + ic0 + ii) * 3 + k];
            }
        }
#pragma unroll
        for (int kk = 0; kk < 16; kk++) {
            float xv[10];
            *(float4*)&xv[0] = *(const float4*)&xs[kk][tn << 3];
            *(float4*)&xv[4] = *(const float4*)&xs[kk][(tn << 3) + 4];
            xv[8] = xs[kk][(tn << 3) + 8];
            xv[9] = xs[kk][(tn << 3) + 9];
            u64 xd[10];
#pragma unroll
            for (int tt = 0; tt < 10; tt++) xd[tt] = dup2(xv[tt]);
#pragma unroll
            for (int k = 0; k < 3; k++) {
                const ulonglong2 wp = *(const ulonglong2*)&ws[kk][k * 68 + (tm << 2)];
#pragma unroll
                for (int j = 0; j < 8; j++) {
                    fma2(accP[0][j], wp.x, xd[j + k]);
                    fma2(accP[1][j], wp.y, xd[j + k]);
                }
            }
        }
    }
    float r[4][8];
#pragma unroll
    for (int j = 0; j < 8; j++) {
        float2 u0 = up2(accP[0][j]), u1 = up2(accP[1][j]);
        r[0][j] = u0.x; r[1][j] = u0.y; r[2][j] = u1.x; r[3][j] = u1.y;
    }
#pragma unroll
    for (int i = 0; i < 4; i++) {
        int m = m0 + (tm << 2) + i;
        float bb = bias[m];
        long off = ((long)b * OCout + m) * WID + n0 + (tn << 3);
        float4 v0, v1;
        v0.x = fmaxf(r[i][0] + bb, 0.f); v0.y = fmaxf(r[i][1] + bb, 0.f);
        v0.z = fmaxf(r[i][2] + bb, 0.f); v0.w = fmaxf(r[i][3] + bb, 0.f);
        v1.x = fmaxf(r[i][4] + bb, 0.f); v1.y = fmaxf(r[i][5] + bb, 0.f);
        v1.z = fmaxf(r[i][6] + bb, 0.f); v1.w = fmaxf(r[i][7] + bb, 0.f);
        if (FINAL) {
            long soff = ((long)b * CH + m) * WID + n0 + (tn << 3);
            float4 s0 = *(const float4*)(SRC + soff);
            float4 s1 = *(const float4*)(SRC + soff + 4);
            v0.x += s0.x; v0.y += s0.y; v0.z += s0.z; v0.w += s0.w;
            v1.x += s1.x; v1.y += s1.y; v1.z += s1.z; v1.w += s1.w;
        }
        *(float4*)(Y + off) = v0;
        *(float4*)(Y + off + 4) = v1;
    }
}

// ---------------- launch ----------------
extern "C" void kernel_launch(void* const* d_in, const int* in_sizes, int n_in,
                              void* d_out, int out_size) {
    const float* src     = (const float*)d_in[0];
    const float* w_theta = (const float*)d_in[1];
    const float* w_phi   = (const float*)d_in[2];
    const float* w_g     = (const float*)d_in[3];
    const float* w_o     = (const float*)d_in[4];
    const float* gamma   = (const float*)d_in[5];
    const float* w_c1 = (const float*)d_in[6];  const float* b_c1 = (const float*)d_in[7];
    const float* w_c2 = (const float*)d_in[8];  const float* b_c2 = (const float*)d_in[9];
    const float* w_c3 = (const float*)d_in[10]; const float* b_c3 = (const float*)d_in[11];
    const float* w_c4 = (const float*)d_in[12]; const float* b_c4 = (const float*)d_in[13];
    float* out = (float*)d_out;

    static float *p_wpack = nullptr, *p_proj, *p_phir, *p_gr, *p_attn, *p_ag,
                 *p_x, *p_h1, *p_h2, *p_gram;
    if (!p_wpack) {
        cudaGetSymbolAddress((void**)&p_wpack, g_wpack);
        cudaGetSymbolAddress((void**)&p_proj,  g_proj);
        cudaGetSymbolAddress((void**)&p_phir,  g_phir);
        cudaGetSymbolAddress((void**)&p_gr,    g_gr);
        cudaGetSymbolAddress((void**)&p_attn,  g_attn);
        cudaGetSymbolAddress((void**)&p_ag,    g_ag);
        cudaGetSymbolAddress((void**)&p_x,     g_x);
        cudaGetSymbolAddress((void**)&p_h1,    g_h1);
        cudaGetSymbolAddress((void**)&p_h2,    g_h2);
        cudaGetSymbolAddress((void**)&p_gram,  g_gram);
    }

    // 1) pack projection weights, run projections [768,2048] per batch
    k_pack<<<3072, 256>>>(w_theta, w_phi, w_g);
    k_gemm<0, 0, 0><<<dim3(32, 6, 4), 256>>>(p_wpack, src, p_proj,
        768, 2048, 1024, 0, 2097152, 1572864, nullptr, 0, nullptr);
    // 2) pools (flat reshape is free)
    k_pool<<<1024, 256>>>(0);
    k_pool<<<4096, 256>>>(1);
    // 3) Gram matrices via the same GEMM
    k_gemm<0, 1, 0><<<dim3(2, 1, 1), 256>>>(w_theta, w_theta, p_gram,
        128, 128, 1024, 0, 0, 0, nullptr, 0, nullptr);
    k_gemm<0, 1, 0><<<dim3(2, 1, 1), 256>>>(w_phi, w_phi, p_gram + 262144,
        128, 128, 1024, 0, 0, 0, nullptr, 0, nullptr);
    k_gemm<0, 1, 0><<<dim3(8, 4, 1), 256>>>(w_g, w_g, p_gram + 524288,
        512, 512, 1024, 0, 0, 0, nullptr, 0, nullptr);
    k_gemm<1, 0, 0><<<dim3(8, 4, 1), 256>>>(w_o, w_o, p_gram + 786432,
        512, 512, 1024, 0, 0, 0, nullptr, 0, nullptr);
    // 4) trace-power chain for spectral norms (K=10 : power 1024, ample)
    k_trace<<<4, 512>>>(0, 0);
    for (int s = 1; s <= 10; s++) {
        k_sq<<<dim3(2, 1, 2), 256>>>((s - 1) & 1, s, 0);
        k_sq<<<dim3(8, 4, 2), 256>>>((s - 1) & 1, s, 1);
        k_trace<<<4, 512>>>(s, s & 1);
    }
    k_sigfinal<<<1, 4>>>(10);
    // 5) logits = theta^T @ phi_r, scaled 1/(sig_t*sig_p), then softmax
    k_gemm<1, 0, 1><<<dim3(8, 16, 4), 256>>>(p_proj, p_phir, p_attn,
        2048, 512, 128, 1572864, 65536, 1048576, nullptr, 0, nullptr);
    k_softmax<<<1024, 256>>>();
    // 6) attn_g = g_r @ attn^T, scaled 1/sig_g
    k_gemm<0, 1, 2><<<dim3(32, 4, 4), 256>>>(p_gr, p_attn, p_ag,
        512, 2048, 512, 262144, 1048576, 1048576, nullptr, 0, nullptr);
    // 7) x = 2*src + (gamma/sig_o) * (w_o @ attn_g)
    k_gemm<0, 0, 3><<<dim3(32, 8, 4), 256>>>(w_o, p_ag, p_x,
        1024, 2048, 512, 0, 1048576, 2097152, src, 2097152, gamma);
    // 8) conv FFN
    k_conv<0><<<dim3(16, 8, 4), 256>>>(p_x,  w_c1, b_c1, p_h1, 1024, 512, nullptr);
    k_conv<0><<<dim3(16, 8, 4), 256>>>(p_h1, w_c2, b_c2, p_h2, 512, 512, nullptr);
    k_conv<0><<<dim3(16, 8, 4), 256>>>(p_h2, w_c3, b_c3, p_h1, 512, 512, nullptr);
    k_conv<1><<<dim3(16, 16, 4), 256>>>(p_h1, w_c4, b_c4, out, 512, 1024, src);
    (void)in_sizes; (void)n_in; (void)out_size;
}

// round 14
// speedup vs baseline: 1.1749x; 1.0957x over previous
#include <cuda_runtime.h>
#include <cuda_bf16.h>
#include <math.h>

#define BATCH 4
#define CH    1024
#define WID   2048
#define OC    512

typedef unsigned long long u64;
typedef unsigned int u32;

__device__ __forceinline__ u64 dup2(float v) {
    u64 r; asm("mov.b64 %0,{%1,%1};" : "=l"(r) : "f"(v)); return r;
}
__device__ __forceinline__ void fma2(u64& c, u64 a, u64 b) {
    asm("fma.rn.f32x2 %0,%1,%2,%0;" : "+l"(c) : "l"(a), "l"(b));
}
__device__ __forceinline__ float2 up2(u64 v) {
    float2 f; asm("mov.b64 {%0,%1},%2;" : "=f"(f.x), "=f"(f.y) : "l"(v)); return f;
}
__device__ __forceinline__ u32 smem_u32(const void* p) {
    u32 a; asm("{ .reg .u64 t; cvta.to.shared.u64 t, %1; cvt.u32.u64 %0, t; }"
               : "=r"(a) : "l"(p));
    return a;
}
__device__ __forceinline__ void cpasync(u32 dst, const void* src, u32 sz) {
    asm volatile("cp.async.ca.shared.global [%0], [%1], 16, %2;"
                 :: "r"(dst), "l"(src), "r"(sz));
}
#define CP_COMMIT() asm volatile("cp.async.commit_group;" ::: "memory")
#define LDM4(r, addr)                                                        \
    asm volatile("ldmatrix.sync.aligned.m8n8.x4.shared.b16 {%0,%1,%2,%3}, [%4];" \
        : "=r"((r)[0]), "=r"((r)[1]), "=r"((r)[2]), "=r"((r)[3]) : "r"(addr))
#define MMA(d, a, b0, b1)                                                    \
    asm volatile("mma.sync.aligned.m16n8k16.row.col.f32.bf16.bf16.f32 "      \
        "{%0,%1,%2,%3}, {%4,%5,%6,%7}, {%8,%9}, {%0,%1,%2,%3};"              \
        : "+f"((d)[0]), "+f"((d)[1]), "+f"((d)[2]), "+f"((d)[3])             \
        : "r"((a)[0]), "r"((a)[1]), "r"((a)[2]), "r"((a)[3]), "r"(b0), "r"(b1))

// ---------------- scratch ----------------
__device__ float g_wpack[768 * 1024];
__device__ float g_proj[BATCH * 768 * WID];
__device__ float g_phir[BATCH * 128 * 512];
__device__ float g_gr[BATCH * 512 * 512];
__device__ float g_attn[(long)BATCH * WID * 512];
__device__ float g_ag[(long)BATCH * 512 * WID];
__device__ float g_x[(long)BATCH * CH * WID];
__device__ float g_gram[2][4 * 512 * 512];
__device__ float g_tr[16][4];
__device__ float g_sig[4];
// conv bf16 hi/lo activations ([w_global][ic] row-major)
__device__ __nv_bfloat16 g_xt1h[8192L * 1024], g_xt1l[8192L * 1024];
__device__ __nv_bfloat16 g_xt2h[8192L * 512],  g_xt2l[8192L * 512];
__device__ __nv_bfloat16 g_xt3h[8192L * 512],  g_xt3l[8192L * 512];
__device__ __nv_bfloat16 g_xt4h[8192L * 512],  g_xt4l[8192L * 512];
// conv weights repacked [k][oc][ic] hi/lo
__device__ __nv_bfloat16 g_w1h[3L * 512 * 1024], g_w1l[3L * 512 * 1024];
__device__ __nv_bfloat16 g_w2h[3L * 512 * 512],  g_w2l[3L * 512 * 512];
__device__ __nv_bfloat16 g_w3h[3L * 512 * 512],  g_w3l[3L * 512 * 512];
__device__ __nv_bfloat16 g_w4h[3L * 1024 * 512], g_w4l[3L * 1024 * 512];

// ---------------- pack theta|phi|g into [768,1024] ----------------
__global__ void k_pack(const float* __restrict__ wt, const float* __restrict__ wp,
                       const float* __restrict__ wg) {
    int i = blockIdx.x * 256 + threadIdx.x;
    if (i >= 768 * 1024) return;
    int r = i >> 10;
    g_wpack[i] = (r < 128) ? wt[i] : (r < 256) ? wp[i - 131072] : wg[i - 262144];
}

// ---------------- generic tiled GEMM 128x64, micro 8x4, f32x2 packed ----------
template <int AKM, int BNK, int EPI>
__global__ void __launch_bounds__(256) k_gemm(
    const float* __restrict__ A, const float* __restrict__ B, float* __restrict__ C,
    int M, int N, int K, long sA, long sB, long sC,
    const float* __restrict__ aux, long sAux, const float* __restrict__ gma) {
    const int t = threadIdx.x;
    const int bz = blockIdx.z;
    A += (long)bz * sA;  B += (long)bz * sB;  C += (long)bz * sC;
    const int m0 = blockIdx.y * 128, n0 = blockIdx.x * 64;
    __shared__ float As[16][132];
    __shared__ float Bs[16][68];
    const int tm = t >> 4, tn = t & 15;
    u64 acc[4][4];
#pragma unroll
    for (int i = 0; i < 4; i++)
#pragma unroll
        for (int j = 0; j < 4; j++) acc[i][j] = 0ull;

    float4 ra0, ra1, rb0;
    const int nk = K >> 4;
    {
        if (AKM) {
            int kk = t >> 5, mm = (t & 31) << 2;
            ra0 = *(const float4*)(A + (long)kk * M + m0 + mm);
            ra1 = *(const float4*)(A + (long)(kk + 8) * M + m0 + mm);
        } else {
            int mr = t >> 2, kv = (t & 3) << 2;
            ra0 = *(const float4*)(A + (long)(m0 + mr) * K + kv);
            ra1 = *(const float4*)(A + (long)(m0 + mr + 64) * K + kv);
        }
        if (!BNK) {
            int kk = t >> 4, nv = (t & 15) << 2;
            rb0 = *(const float4*)(B + (long)kk * N + n0 + nv);
        } else {
            int nr = t >> 2, kv = (t & 3) << 2;
            rb0 = *(const float4*)(B + (long)(n0 + nr) * K + kv);
        }
    }
    for (int kc = 0; kc < nk; kc++) {
        if (kc) __syncthreads();
        if (AKM) {
            int kk = t >> 5, mm = (t & 31) << 2;
            *(float4*)&As[kk][mm] = ra0;
            *(float4*)&As[kk + 8][mm] = ra1;
        } else {
            int mr = t >> 2, kv = (t & 3) << 2;
            As[kv + 0][mr] = ra0.x; As[kv + 1][mr] = ra0.y;
            As[kv + 2][mr] = ra0.z; As[kv + 3][mr] = ra0.w;
            As[kv + 0][mr + 64] = ra1.x; As[kv + 1][mr + 64] = ra1.y;
            As[kv + 2][mr + 64] = ra1.z; As[kv + 3][mr + 64] = ra1.w;
        }
        if (!BNK) {
            int kk = t >> 4, nv = (t & 15) << 2;
            *(float4*)&Bs[kk][nv] = rb0;
        } else {
            int nr = t >> 2, kv = (t & 3) << 2;
            Bs[kv + 0][nr] = rb0.x; Bs[kv + 1][nr] = rb0.y;
            Bs[kv + 2][nr] = rb0.z; Bs[kv + 3][nr] = rb0.w;
        }
        __syncthreads();
        if (kc + 1 < nk) {
            int k0 = (kc + 1) << 4;
            if (AKM) {
                int kk = t >> 5, mm = (t & 31) << 2;
                ra0 = *(const float4*)(A + (long)(k0 + kk) * M + m0 + mm);
                ra1 = *(const float4*)(A + (long)(k0 + kk + 8) * M + m0 + mm);
            } else {
                int mr = t >> 2, kv = (t & 3) << 2;
                ra0 = *(const float4*)(A + (long)(m0 + mr) * K + k0 + kv);
                ra1 = *(const float4*)(A + (long)(m0 + mr + 64) * K + k0 + kv);
            }
            if (!BNK) {
                int kk = t >> 4, nv = (t & 15) << 2;
                rb0 = *(const float4*)(B + (long)(k0 + kk) * N + n0 + nv);
            } else {
                int nr = t >> 2, kv = (t & 3) << 2;
                rb0 = *(const float4*)(B + (long)(n0 + nr) * K + k0 + kv);
            }
        }
#pragma unroll
        for (int kk = 0; kk < 16; kk++) {
            const ulonglong2 a01 = *(const ulonglong2*)&As[kk][tm << 3];
            const ulonglong2 a23 = *(const ulonglong2*)&As[kk][(tm << 3) + 4];
            const float4 bv = *(const float4*)&Bs[kk][tn << 2];
            u64 b0 = dup2(bv.x), b1 = dup2(bv.y), b2 = dup2(bv.z), b3 = dup2(bv.w);
            fma2(acc[0][0], a01.x, b0); fma2(acc[0][1], a01.x, b1);
            fma2(acc[0][2], a01.x, b2); fma2(acc[0][3], a01.x, b3);
            fma2(acc[1][0], a01.y, b0); fma2(acc[1][1], a01.y, b1);
            fma2(acc[1][2], a01.y, b2); fma2(acc[1][3], a01.y, b3);
            fma2(acc[2][0], a23.x, b0); fma2(acc[2][1], a23.x, b1);
            fma2(acc[2][2], a23.x, b2); fma2(acc[2][3], a23.x, b3);
            fma2(acc[3][0], a23.y, b0); fma2(acc[3][1], a23.y, b1);
            fma2(acc[3][2], a23.y, b2); fma2(acc[3][3], a23.y, b3);
        }
    }
    float sc = 1.f, gm = 0.f;
    if (EPI == 1) sc = 1.f / (g_sig[0] * g_sig[1]);
    else if (EPI == 2) sc = 1.f / g_sig[2];
    else if (EPI == 3) gm = gma[0] / g_sig[3];
#pragma unroll
    for (int p = 0; p < 4; p++) {
        float va[4], vb[4];
#pragma unroll
        for (int j = 0; j < 4; j++) {
            float2 u = up2(acc[p][j]);
            va[j] = u.x; vb[j] = u.y;
        }
#pragma unroll
        for (int h = 0; h < 2; h++) {
            const float* r = h ? vb : va;
            int m = m0 + (tm << 3) + 2 * p + h;
            long off = (long)m * N + n0 + (tn << 2);
            float4 v;
            if (EPI == 3) {
                float4 s4 = *(const float4*)(aux + (long)bz * sAux + off);
                v.x = 2.f * s4.x + gm * r[0];
                v.y = 2.f * s4.y + gm * r[1];
                v.z = 2.f * s4.z + gm * r[2];
                v.w = 2.f * s4.w + gm * r[3];
            } else {
                v.x = r[0] * sc; v.y = r[1] * sc;
                v.z = r[2] * sc; v.w = r[3] * sc;
            }
            *(float4*)(C + off) = v;
        }
    }
}

// ---------------- trace-normalized squaring: C = (A/t)^2 ----------------
__global__ void __launch_bounds__(256) k_sq(int srcbuf, int step, int mpair) {
    const int j = (mpair ? 2 : 0) + blockIdx.z;
    const int m = mpair ? 512 : 128;
    const float* __restrict__ A = &g_gram[srcbuf][j * 262144];
    float* __restrict__ C = &g_gram[srcbuf ^ 1][j * 262144];
    const float inv = 1.0f / g_tr[step - 1][j];
    const int t = threadIdx.x;
    const int m0 = blockIdx.y * 128, n0 = blockIdx.x * 64;
    __shared__ float As[16][132];
    __shared__ float Bs[16][68];
    const int tm = t >> 4, tn = t & 15;
    u64 acc[4][4];
#pragma unroll
    for (int i = 0; i < 4; i++)
#pragma unroll
        for (int j2 = 0; j2 < 4; j2++) acc[i][j2] = 0ull;
    const int nk = m >> 4;
    const int mr = t >> 2, kv = (t & 3) << 2;
    const int kkb = t >> 4, nv = (t & 15) << 2;
    float4 ra0 = *(const float4*)(A + (long)(m0 + mr) * m + kv);
    float4 ra1 = *(const float4*)(A + (long)(m0 + mr + 64) * m + kv);
    float4 rb0 = *(const float4*)(A + (long)kkb * m + n0 + nv);
    for (int kc = 0; kc < nk; kc++) {
        if (kc) __syncthreads();
        As[kv + 0][mr] = ra0.x; As[kv + 1][mr] = ra0.y;
        As[kv + 2][mr] = ra0.z; As[kv + 3][mr] = ra0.w;
        As[kv + 0][mr + 64] = ra1.x; As[kv + 1][mr + 64] = ra1.y;
        As[kv + 2][mr + 64] = ra1.z; As[kv + 3][mr + 64] = ra1.w;
        *(float4*)&Bs[kkb][nv] = rb0;
        __syncthreads();
        if (kc + 1 < nk) {
            int k0 = (kc + 1) << 4;
            ra0 = *(const float4*)(A + (long)(m0 + mr) * m + k0 + kv);
            ra1 = *(const float4*)(A + (long)(m0 + mr + 64) * m + k0 + kv);
            rb0 = *(const float4*)(A + (long)(k0 + kkb) * m + n0 + nv);
        }
#pragma unroll
        for (int kk = 0; kk < 16; kk++) {
            const ulonglong2 a01 = *(const ulonglong2*)&As[kk][tm << 3];
            const ulonglong2 a23 = *(const ulonglong2*)&As[kk][(tm << 3) + 4];
            const float4 bv = *(const float4*)&Bs[kk][tn << 2];
            u64 b0 = dup2(bv.x), b1 = dup2(bv.y), b2 = dup2(bv.z), b3 = dup2(bv.w);
            fma2(acc[0][0], a01.x, b0); fma2(acc[0][1], a01.x, b1);
            fma2(acc[0][2], a01.x, b2); fma2(acc[0][3], a01.x, b3);
            fma2(acc[1][0], a01.y, b0); fma2(acc[1][1], a01.y, b1);
            fma2(acc[1][2], a01.y, b2); fma2(acc[1][3], a01.y, b3);
            fma2(acc[2][0], a23.x, b0); fma2(acc[2][1], a23.x, b1);
            fma2(acc[2][2], a23.x, b2); fma2(acc[2][3], a23.x, b3);
            fma2(acc[3][0], a23.y, b0); fma2(acc[3][1], a23.y, b1);
            fma2(acc[3][2], a23.y, b2); fma2(acc[3][3], a23.y, b3);
        }
    }
    float s2 = inv * inv;
#pragma unroll
    for (int p = 0; p < 4; p++) {
        float2 u0 = up2(acc[p][0]), u1 = up2(acc[p][1]),
               u2 = up2(acc[p][2]), u3 = up2(acc[p][3]);
        long offA = (long)(m0 + (tm << 3) + 2 * p) * m + n0 + (tn << 2);
        float4 v;
        v.x = u0.x * s2; v.y = u1.x * s2; v.z = u2.x * s2; v.w = u3.x * s2;
        *(float4*)(C + offA) = v;
        v.x = u0.y * s2; v.y = u1.y * s2; v.z = u2.y * s2; v.w = u3.y * s2;
        *(float4*)(C + offA + m) = v;
    }
}

__global__ void k_trace(int step, int srcbuf) {
    int j = blockIdx.x;
    int m = (j < 2) ? 128 : 512;
    const float* A = &g_gram[srcbuf][j * 262144];
    __shared__ float red[512];
    float s = 0.f;
    for (int i = threadIdx.x; i < m; i += 512) s += A[(long)i * m + i];
    red[threadIdx.x] = s;
    __syncthreads();
    for (int o = 256; o > 0; o >>= 1) {
        if (threadIdx.x < o) red[threadIdx.x] += red[threadIdx.x + o];
        __syncthreads();
    }
    if (threadIdx.x == 0) g_tr[step][j] = red[0];
}

__global__ void k_sigfinal(int K) {
    int j = threadIdx.x;
    if (j >= 4) return;
    double la = 0.0, p = 1.0;
    for (int k = 0; k < K; k++) { la += log((double)g_tr[k][j]) * p; p *= 0.5; }
    la += log((double)g_tr[K][j]) * p;
    g_sig[j] = (float)exp(0.5 * la);
}

// ---------------- 2x2 maxpool over (c,w) + flat reshape ----------------
__global__ void k_pool(int which) {
    int C2 = which ? 256 : 64;
    int rowbase = which ? 256 : 128;
    float* out = which ? g_gr : g_phir;
    int total = BATCH * C2 * 1024;
    int i = blockIdx.x * 256 + threadIdx.x;
    if (i >= total) return;
    int w2 = i & 1023;
    int c2 = (i >> 10) % C2;
    int b = i / (C2 << 10);
    const float* P = &g_proj[((long)b * 768 + rowbase + 2 * c2) * WID + 2 * w2];
    float v = fmaxf(fmaxf(P[0], P[1]), fmaxf(P[WID], P[WID + 1]));
    out[(long)b * ((long)C2 << 10) + c2 * 1024 + w2] = v;
}

// ---------------- row softmax over 512 ----------------
__global__ void k_softmax() {
    int row = blockIdx.x * 8 + (threadIdx.x >> 5);
    int lane = threadIdx.x & 31;
    float* p = g_attn + (long)row * 512;
    float v[16];
#pragma unroll
    for (int r = 0; r < 4; r++)
        *(float4*)&v[r * 4] = *(const float4*)&p[r * 128 + lane * 4];
    float mx = v[0];
#pragma unroll
    for (int i = 1; i < 16; i++) mx = fmaxf(mx, v[i]);
#pragma unroll
    for (int o = 16; o > 0; o >>= 1) mx = fmaxf(mx, __shfl_xor_sync(0xffffffffu, mx, o));
    float s = 0.f;
#pragma unroll
    for (int i = 0; i < 16; i++) { v[i] = __expf(v[i] - mx); s += v[i]; }
#pragma unroll
    for (int o = 16; o > 0; o >>= 1) s += __shfl_xor_sync(0xffffffffu, s, o);
    float inv = 1.f / s;
#pragma unroll
    for (int i = 0; i < 16; i++) v[i] *= inv;
#pragma unroll
    for (int r = 0; r < 4; r++)
        *(float4*)&p[r * 128 + lane * 4] = *(const float4*)&v[r * 4];
}

// -------- transpose + hi/lo split: g_x [b][ch][w] -> Xt1 [b*2048+w][ch] ------
__global__ void k_tcvt(const float* __restrict__ X,
                       __nv_bfloat16* __restrict__ Xh, __nv_bfloat16* __restrict__ Xl) {
    __shared__ float tile[32][33];
    int b = blockIdx.z, w0 = blockIdx.x * 32, c0 = blockIdx.y * 32;
    int tx = threadIdx.x, ty = threadIdx.y;   // 32 x 8
#pragma unroll
    for (int i = 0; i < 4; i++)
        tile[ty + i * 8][tx] = X[((long)b * 1024 + c0 + ty + i * 8) * 2048 + w0 + tx];
    __syncthreads();
#pragma unroll
    for (int i = 0; i < 4; i++) {
        float v = tile[tx][ty + i * 8];
        long o = ((long)(b * 2048 + w0 + ty + i * 8)) * 1024 + c0 + tx;
        __nv_bfloat16 h = __float2bfloat16(v);
        Xh[o] = h;
        Xl[o] = __float2bfloat16(v - __bfloat162float(h));
    }
}

// -------- weight repack: w[oc][ic][k] -> W[k][oc][ic] hi/lo ------------------
__global__ void k_wprep(const float* __restrict__ w,
                        __nv_bfloat16* __restrict__ Wh, __nv_bfloat16* __restrict__ Wl,
                        int OCt, int ICt) {
    long n = (long)OCt * ICt * 3;
    long i = (long)blockIdx.x * 256 + threadIdx.x;
    if (i >= n) return;
    int k = (int)(i / ((long)OCt * ICt));
    long rem = i - (long)k * OCt * ICt;
    int oc = (int)(rem / ICt), ic = (int)(rem % ICt);
    float v = w[((long)oc * ICt + ic) * 3 + k];
    __nv_bfloat16 h = __float2bfloat16(v);
    Wh[i] = h;
    Wl[i] = __float2bfloat16(v - __bfloat162float(h));
}

// -------- conv1d k=3 'same' via mma.sync HMMA, bf16x3 split ------------------
// CTA tile: 128 (w) x 128 (oc). 8 warps, each 64x32 (4 m16 x 4 n8).
// K-chunks of 32 ic; 3 kshifts. cp.async double-buffered smem:
// per stage: Ah(10240) Al(10240) Bh(10240) Bl(10240), row stride 80B.
template <int FINAL>
__global__ void __launch_bounds__(256) k_convhmma(
    const __nv_bfloat16* __restrict__ Xh, const __nv_bfloat16* __restrict__ Xl,
    const __nv_bfloat16* __restrict__ Wh, const __nv_bfloat16* __restrict__ Wl,
    const float* __restrict__ bias, int IC, int OCt,
    __nv_bfloat16* __restrict__ Yh, __nv_bfloat16* __restrict__ Yl,
    float* __restrict__ Yt) {
    extern __shared__ char dsm[];
    const int t = threadIdx.x, lane = t & 31, wid = t >> 5;
    const int oc0 = blockIdx.x * 128;
    const int Mtile = blockIdx.y;
    const int bb = Mtile >> 4, w0 = (Mtile & 15) << 7;
    const int wm = wid >> 2, wn = wid & 3;
    const u32 smb = smem_u32(dsm);
    const int nic = IC >> 5;
    const int C = 3 * nic;

    float acc[4][4][4];
#pragma unroll
    for (int a = 0; a < 4; a++)
#pragma unroll
        for (int b = 0; b < 4; b++)
#pragma unroll
            for (int c = 0; c < 4; c++) acc[a][b][c] = 0.f;

    auto load_stage = [&](int c) {
        const int kshift = c / nic;
        const int icc = (c - kshift * nic) << 5;
        const u32 sb = smb + (u32)(c & 1) * 40960u;
#pragma unroll
        for (int i = 0; i < 2; i++) {
            int s = t + i * 256;
            int row = s >> 2, segc = (s & 3) << 4;
            int wl = w0 + row + kshift - 1;
            u32 ok = (wl >= 0 && wl < 2048) ? 16u : 0u;
            int wcl = wl < 0 ? 0 : (wl > 2047 ? 2047 : wl);
            long ga = ((long)(bb * 2048 + wcl) * IC + icc) * 2 + segc;
            u32 soA = sb + row * 80 + segc;
            cpasync(soA, (const char*)Xh + ga, ok);
            cpasync(soA + 10240, (const char*)Xl + ga, ok);
            long gb = ((long)(kshift * OCt + oc0 + row) * IC + icc) * 2 + segc;
            u32 soB = sb + 20480 + row * 80 + segc;
            cpasync(soB, (const char*)Wh + gb, 16u);
            cpasync(soB + 10240, (const char*)Wl + gb, 16u);
        }
        CP_COMMIT();
    };

    load_stage(0);
    if (C > 1) load_stage(1);

    for (int c = 0; c < C; c++) {
        if (c + 1 < C) asm volatile("cp.async.wait_group 1;" ::: "memory");
        else           asm volatile("cp.async.wait_group 0;" ::: "memory");
        __syncthreads();
        const u32 sb = smb + (u32)(c & 1) * 40960u;
        const u32 aB = sb + (u32)(wm * 64 + (lane & 15)) * 80 + (u32)((lane >> 4) << 4);
        const u32 bB = sb + 20480u
                       + (u32)(wn * 32 + (lane & 7) + ((lane >> 4) << 3)) * 80
                       + (u32)(((lane >> 3) & 1) << 4);
#pragma unroll
        for (int ks = 0; ks < 2; ks++) {
            u32 AH[16], AL2[16], BH[8], BL[8];
#pragma unroll
            for (int mt = 0; mt < 4; mt++) {
                u32 a = aB + ks * 32 + mt * (16 * 80);
                LDM4(AH + mt * 4, a);
                LDM4(AL2 + mt * 4, a + 10240);
            }
#pragma unroll
            for (int np = 0; np < 2; np++) {
                u32 b = bB + ks * 32 + np * (16 * 80);
                LDM4(BH + np * 4, b);
                LDM4(BL + np * 4, b + 10240);
            }
#pragma unroll
            for (int mt = 0; mt < 4; mt++)
#pragma unroll
                for (int nt = 0; nt < 4; nt++) {
                    const int bi = (nt >> 1) * 4 + (nt & 1) * 2;
                    MMA(acc[mt][nt], AH + mt * 4, BH[bi], BH[bi + 1]);
                    MMA(acc[mt][nt], AH + mt * 4, BL[bi], BL[bi + 1]);
                    MMA(acc[mt][nt], AL2 + mt * 4, BH[bi], BH[bi + 1]);
                }
        }
        __syncthreads();
        if (c + 2 < C) load_stage(c + 2);
    }

    // epilogue
    const int mrb = wm * 64 + (lane >> 2);
#pragma unroll
    for (int mt = 0; mt < 4; mt++) {
        const int mr = mrb + mt * 16;
        const long grow = (long)Mtile * 128 + mr;
#pragma unroll
        for (int nt = 0; nt < 4; nt++) {
            const int oc = oc0 + wn * 32 + nt * 8 + ((lane & 3) << 1);
            const float b0v = __ldg(bias + oc), b1v = __ldg(bias + oc + 1);
            float v00 = fmaxf(acc[mt][nt][0] + b0v, 0.f);
            float v01 = fmaxf(acc[mt][nt][1] + b1v, 0.f);
            float v10 = fmaxf(acc[mt][nt][2] + b0v, 0.f);
            float v11 = fmaxf(acc[mt][nt][3] + b1v, 0.f);
            if (FINAL) {
                *(float2*)(Yt + grow * OCt + oc) = make_float2(v00, v01);
                *(float2*)(Yt + (grow + 8) * OCt + oc) = make_float2(v10, v11);
            } else {
                __nv_bfloat16 h0 = __float2bfloat16(v00);
                __nv_bfloat16 h1 = __float2bfloat16(v01);
                __nv_bfloat16 h2 = __float2bfloat16(v10);
                __nv_bfloat16 h3 = __float2bfloat16(v11);
                u32 hp0 = (u32)__bfloat16_as_ushort(h0) |
                          ((u32)__bfloat16_as_ushort(h1) << 16);
                u32 hp1 = (u32)__bfloat16_as_ushort(h2) |
                          ((u32)__bfloat16_as_ushort(h3) << 16);
                __nv_bfloat16 l0 = __float2bfloat16(v00 - __bfloat162float(h0));
                __nv_bfloat16 l1 = __float2bfloat16(v01 - __bfloat162float(h1));
                __nv_bfloat16 l2 = __float2bfloat16(v10 - __bfloat162float(h2));
                __nv_bfloat16 l3 = __float2bfloat16(v11 - __bfloat162float(h3));
                u32 lp0 = (u32)__bfloat16_as_ushort(l0) |
                          ((u32)__bfloat16_as_ushort(l1) << 16);
                u32 lp1 = (u32)__bfloat16_as_ushort(l2) |
                          ((u32)__bfloat16_as_ushort(l3) << 16);
                *(u32*)(Yh + grow * OCt + oc) = hp0;
                *(u32*)(Yh + (grow + 8) * OCt + oc) = hp1;
                *(u32*)(Yl + grow * OCt + oc) = lp0;
                *(u32*)(Yl + (grow + 8) * OCt + oc) = lp1;
            }
        }
    }
}

// -------- final transpose + residual: out[b][oc][w] = T[b*2048+w][oc]+src ----
__global__ void k_fin(const float* __restrict__ T, const float* __restrict__ src,
                      float* __restrict__ out) {
    __shared__ float tile[32][33];
    int b = blockIdx.z, w0 = blockIdx.x * 32, c0 = blockIdx.y * 32;
    int tx = threadIdx.x, ty = threadIdx.y;   // 32 x 8
#pragma unroll
    for (int i = 0; i < 4; i++)
        tile[ty + i * 8][tx] = T[((long)(b * 2048 + w0 + ty + i * 8)) * 1024 + c0 + tx];
    __syncthreads();
#pragma unroll
    for (int i = 0; i < 4; i++) {
        long o = ((long)(b * 1024 + c0 + ty + i * 8)) * 2048 + w0 + tx;
        out[o] = tile[tx][ty + i * 8] + src[o];
    }
}

// ---------------- launch ----------------
extern "C" void kernel_launch(void* const* d_in, const int* in_sizes, int n_in,
                              void* d_out, int out_size) {
    const float* src     = (const float*)d_in[0];
    const float* w_theta = (const float*)d_in[1];
    const float* w_phi   = (const float*)d_in[2];
    const float* w_g     = (const float*)d_in[3];
    const float* w_o     = (const float*)d_in[4];
    const float* gamma   = (const float*)d_in[5];
    const float* w_c1 = (const float*)d_in[6];  const float* b_c1 = (const float*)d_in[7];
    const float* w_c2 = (const float*)d_in[8];  const float* b_c2 = (const float*)d_in[9];
    const float* w_c3 = (const float*)d_in[10]; const float* b_c3 = (const float*)d_in[11];
    const float* w_c4 = (const float*)d_in[12]; const float* b_c4 = (const float*)d_in[13];
    float* out = (float*)d_out;

    static float *p_wpack = nullptr, *p_proj, *p_phir, *p_gr, *p_attn, *p_ag,
                 *p_x, *p_gram;
    static __nv_bfloat16 *x1h, *x1l, *x2h, *x2l, *x3h, *x3l, *x4h, *x4l;
    static __nv_bfloat16 *w1h, *w1l, *w2h, *w2l, *w3h, *w3l, *w4h, *w4l;
    if (!p_wpack) {
        cudaGetSymbolAddress((void**)&p_wpack, g_wpack);
        cudaGetSymbolAddress((void**)&p_proj,  g_proj);
        cudaGetSymbolAddress((void**)&p_phir,  g_phir);
        cudaGetSymbolAddress((void**)&p_gr,    g_gr);
        cudaGetSymbolAddress((void**)&p_attn,  g_attn);
        cudaGetSymbolAddress((void**)&p_ag,    g_ag);
        cudaGetSymbolAddress((void**)&p_x,     g_x);
        cudaGetSymbolAddress((void**)&p_gram,  g_gram);
        cudaGetSymbolAddress((void**)&x1h, g_xt1h); cudaGetSymbolAddress((void**)&x1l, g_xt1l);
        cudaGetSymbolAddress((void**)&x2h, g_xt2h); cudaGetSymbolAddress((void**)&x2l, g_xt2l);
        cudaGetSymbolAddress((void**)&x3h, g_xt3h); cudaGetSymbolAddress((void**)&x3l, g_xt3l);
        cudaGetSymbolAddress((void**)&x4h, g_xt4h); cudaGetSymbolAddress((void**)&x4l, g_xt4l);
        cudaGetSymbolAddress((void**)&w1h, g_w1h);  cudaGetSymbolAddress((void**)&w1l, g_w1l);
        cudaGetSymbolAddress((void**)&w2h, g_w2h);  cudaGetSymbolAddress((void**)&w2l, g_w2l);
        cudaGetSymbolAddress((void**)&w3h, g_w3h);  cudaGetSymbolAddress((void**)&w3l, g_w3l);
        cudaGetSymbolAddress((void**)&w4h, g_w4h);  cudaGetSymbolAddress((void**)&w4l, g_w4l);
        cudaFuncSetAttribute(k_convhmma<0>,
                             cudaFuncAttributeMaxDynamicSharedMemorySize, 81920);
        cudaFuncSetAttribute(k_convhmma<1>,
                             cudaFuncAttributeMaxDynamicSharedMemorySize, 81920);
    }

    // 1) projections
    k_pack<<<3072, 256>>>(w_theta, w_phi, w_g);
    k_gemm<0, 0, 0><<<dim3(32, 6, 4), 256>>>(p_wpack, src, p_proj,
        768, 2048, 1024, 0, 2097152, 1572864, nullptr, 0, nullptr);
    // 2) pools
    k_pool<<<1024, 256>>>(0);
    k_pool<<<4096, 256>>>(1);
    // 3) Gram matrices
    k_gemm<0, 1, 0><<<dim3(2, 1, 1), 256>>>(w_theta, w_theta, p_gram,
        128, 128, 1024, 0, 0, 0, nullptr, 0, nullptr);
    k_gemm<0, 1, 0><<<dim3(2, 1, 1), 256>>>(w_phi, w_phi, p_gram + 262144,
        128, 128, 1024, 0, 0, 0, nullptr, 0, nullptr);
    k_gemm<0, 1, 0><<<dim3(8, 4, 1), 256>>>(w_g, w_g, p_gram + 524288,
        512, 512, 1024, 0, 0, 0, nullptr, 0, nullptr);
    k_gemm<1, 0, 0><<<dim3(8, 4, 1), 256>>>(w_o, w_o, p_gram + 786432,
        512, 512, 1024, 0, 0, 0, nullptr, 0, nullptr);
    // 4) sigma chain
    k_trace<<<4, 512>>>(0, 0);
    for (int s = 1; s <= 10; s++) {
        k_sq<<<dim3(2, 1, 2), 256>>>((s - 1) & 1, s, 0);
        k_sq<<<dim3(8, 4, 2), 256>>>((s - 1) & 1, s, 1);
        k_trace<<<4, 512>>>(s, s & 1);
    }
    k_sigfinal<<<1, 4>>>(10);
    // 5) logits + softmax
    k_gemm<1, 0, 1><<<dim3(8, 16, 4), 256>>>(p_proj, p_phir, p_attn,
        2048, 512, 128, 1572864, 65536, 1048576, nullptr, 0, nullptr);
    k_softmax<<<1024, 256>>>();
    // 6) attn_g
    k_gemm<0, 1, 2><<<dim3(32, 4, 4), 256>>>(p_gr, p_attn, p_ag,
        512, 2048, 512, 262144, 1048576, 1048576, nullptr, 0, nullptr);
    // 7) x = 2*src + (gamma/sig_o) * (w_o @ attn_g)
    k_gemm<0, 0, 3><<<dim3(32, 8, 4), 256>>>(w_o, p_ag, p_x,
        1024, 2048, 512, 0, 1048576, 2097152, src, 2097152, gamma);
    // 8) conv FFN on HMMA (mma.sync), bf16x3
    k_tcvt<<<dim3(64, 32, 4), dim3(32, 8)>>>(p_x, x1h, x1l);
    k_wprep<<<6144, 256>>>(w_c1, w1h, w1l, 512, 1024);
    k_wprep<<<3072, 256>>>(w_c2, w2h, w2l, 512, 512);
    k_wprep<<<3072, 256>>>(w_c3, w3h, w3l, 512, 512);
    k_wprep<<<6144, 256>>>(w_c4, w4h, w4l, 1024, 512);
    k_convhmma<0><<<dim3(4, 64), 256, 81920>>>(x1h, x1l, w1h, w1l, b_c1,
        1024, 512, x2h, x2l, nullptr);
    k_convhmma<0><<<dim3(4, 64), 256, 81920>>>(x2h, x2l, w2h, w2l, b_c2,
        512, 512, x3h, x3l, nullptr);
    k_convhmma<0><<<dim3(4, 64), 256, 81920>>>(x3h, x3l, w3h, w3l, b_c3,
        512, 512, x4h, x4l, nullptr);
    k_convhmma<1><<<dim3(8, 64), 256, 81920>>>(x4h, x4l, w4h, w4l, b_c4,
        512, 1024, nullptr, nullptr, p_x);
    k_fin<<<dim3(64, 32, 4), dim3(32, 8)>>>(p_x, src, out);
    (void)in_sizes; (void)n_in; (void)out_size;
}

// round 15
// speedup vs baseline: 1.8482x; 1.5730x over previous
#include <cuda_runtime.h>
#include <cuda_bf16.h>
#include <math.h>

#define BATCH 4
#define CH    1024
#define WID   2048
#define OC    512

typedef unsigned long long u64;
typedef unsigned int u32;

__device__ __forceinline__ u64 dup2(float v) {
    u64 r; asm("mov.b64 %0,{%1,%1};" : "=l"(r) : "f"(v)); return r;
}
__device__ __forceinline__ void fma2(u64& c, u64 a, u64 b) {
    asm("fma.rn.f32x2 %0,%1,%2,%0;" : "+l"(c) : "l"(a), "l"(b));
}
__device__ __forceinline__ float2 up2(u64 v) {
    float2 f; asm("mov.b64 {%0,%1},%2;" : "=f"(f.x), "=f"(f.y) : "l"(v)); return f;
}
__device__ __forceinline__ u32 smem_u32(const void* p) {
    u32 a; asm("{ .reg .u64 t; cvta.to.shared.u64 t, %1; cvt.u32.u64 %0, t; }"
               : "=r"(a) : "l"(p));
    return a;
}
__device__ __forceinline__ void cpasync(u32 dst, const void* src, u32 sz) {
    asm volatile("cp.async.ca.shared.global [%0], [%1], 16, %2;"
                 :: "r"(dst), "l"(src), "r"(sz));
}
#define CP_COMMIT() asm volatile("cp.async.commit_group;" ::: "memory")
#define LDM4(r, addr)                                                        \
    asm volatile("ldmatrix.sync.aligned.m8n8.x4.shared.b16 {%0,%1,%2,%3}, [%4];" \
        : "=r"((r)[0]), "=r"((r)[1]), "=r"((r)[2]), "=r"((r)[3]) : "r"(addr))
#define MMA(d, a, b0, b1)                                                    \
    asm volatile("mma.sync.aligned.m16n8k16.row.col.f32.bf16.bf16.f32 "      \
        "{%0,%1,%2,%3}, {%4,%5,%6,%7}, {%8,%9}, {%0,%1,%2,%3};"              \
        : "+f"((d)[0]), "+f"((d)[1]), "+f"((d)[2]), "+f"((d)[3])             \
        : "r"((a)[0]), "r"((a)[1]), "r"((a)[2]), "r"((a)[3]), "r"(b0), "r"(b1))

// ---------------- scratch ----------------
__device__ float g_wpack[768 * 1024];
__device__ float g_proj[BATCH * 768 * WID];
__device__ float g_phir[BATCH * 128 * 512];
__device__ float g_gr[BATCH * 512 * 512];
__device__ float g_attn[(long)BATCH * WID * 512];
__device__ float g_ag[(long)BATCH * 512 * WID];
__device__ float g_x[(long)BATCH * CH * WID];
__device__ float g_gram[2][4 * 512 * 512];
__device__ float g_tr[16][4];
__device__ float g_sig[4];
// conv bf16 hi/lo activations ([w_global][ic] row-major)
__device__ __nv_bfloat16 g_xt1h[8192L * 1024], g_xt1l[8192L * 1024];
__device__ __nv_bfloat16 g_xt2h[8192L * 512],  g_xt2l[8192L * 512];
__device__ __nv_bfloat16 g_xt3h[8192L * 512],  g_xt3l[8192L * 512];
__device__ __nv_bfloat16 g_xt4h[8192L * 512],  g_xt4l[8192L * 512];
// conv weights repacked [k][oc][ic] hi/lo
__device__ __nv_bfloat16 g_w1h[3L * 512 * 1024], g_w1l[3L * 512 * 1024];
__device__ __nv_bfloat16 g_w2h[3L * 512 * 512],  g_w2l[3L * 512 * 512];
__device__ __nv_bfloat16 g_w3h[3L * 512 * 512],  g_w3l[3L * 512 * 512];
__device__ __nv_bfloat16 g_w4h[3L * 1024 * 512], g_w4l[3L * 1024 * 512];

// ---------------- pack theta|phi|g into [768,1024] ----------------
__global__ void k_pack(const float* __restrict__ wt, const float* __restrict__ wp,
                       const float* __restrict__ wg) {
    int i = blockIdx.x * 256 + threadIdx.x;
    if (i >= 768 * 1024) return;
    int r = i >> 10;
    g_wpack[i] = (r < 128) ? wt[i] : (r < 256) ? wp[i - 131072] : wg[i - 262144];
}

// ---------------- generic tiled GEMM 128x64, micro 8x4, f32x2 packed ----------
template <int AKM, int BNK, int EPI>
__global__ void __launch_bounds__(256) k_gemm(
    const float* __restrict__ A, const float* __restrict__ B, float* __restrict__ C,
    int M, int N, int K, long sA, long sB, long sC,
    const float* __restrict__ aux, long sAux, const float* __restrict__ gma) {
    const int t = threadIdx.x;
    const int bz = blockIdx.z;
    A += (long)bz * sA;  B += (long)bz * sB;  C += (long)bz * sC;
    const int m0 = blockIdx.y * 128, n0 = blockIdx.x * 64;
    __shared__ float As[16][132];
    __shared__ float Bs[16][68];
    const int tm = t >> 4, tn = t & 15;
    u64 acc[4][4];
#pragma unroll
    for (int i = 0; i < 4; i++)
#pragma unroll
        for (int j = 0; j < 4; j++) acc[i][j] = 0ull;

    float4 ra0, ra1, rb0;
    const int nk = K >> 4;
    {
        if (AKM) {
            int kk = t >> 5, mm = (t & 31) << 2;
            ra0 = *(const float4*)(A + (long)kk * M + m0 + mm);
            ra1 = *(const float4*)(A + (long)(kk + 8) * M + m0 + mm);
        } else {
            int mr = t >> 2, kv = (t & 3) << 2;
            ra0 = *(const float4*)(A + (long)(m0 + mr) * K + kv);
            ra1 = *(const float4*)(A + (long)(m0 + mr + 64) * K + kv);
        }
        if (!BNK) {
            int kk = t >> 4, nv = (t & 15) << 2;
            rb0 = *(const float4*)(B + (long)kk * N + n0 + nv);
        } else {
            int nr = t >> 2, kv = (t & 3) << 2;
            rb0 = *(const float4*)(B + (long)(n0 + nr) * K + kv);
        }
    }
    for (int kc = 0; kc < nk; kc++) {
        if (kc) __syncthreads();
        if (AKM) {
            int kk = t >> 5, mm = (t & 31) << 2;
            *(float4*)&As[kk][mm] = ra0;
            *(float4*)&As[kk + 8][mm] = ra1;
        } else {
            int mr = t >> 2, kv = (t & 3) << 2;
            As[kv + 0][mr] = ra0.x; As[kv + 1][mr] = ra0.y;
            As[kv + 2][mr] = ra0.z; As[kv + 3][mr] = ra0.w;
            As[kv + 0][mr + 64] = ra1.x; As[kv + 1][mr + 64] = ra1.y;
            As[kv + 2][mr + 64] = ra1.z; As[kv + 3][mr + 64] = ra1.w;
        }
        if (!BNK) {
            int kk = t >> 4, nv = (t & 15) << 2;
            *(float4*)&Bs[kk][nv] = rb0;
        } else {
            int nr = t >> 2, kv = (t & 3) << 2;
            Bs[kv + 0][nr] = rb0.x; Bs[kv + 1][nr] = rb0.y;
            Bs[kv + 2][nr] = rb0.z; Bs[kv + 3][nr] = rb0.w;
        }
        __syncthreads();
        if (kc + 1 < nk) {
            int k0 = (kc + 1) << 4;
            if (AKM) {
                int kk = t >> 5, mm = (t & 31) << 2;
                ra0 = *(const float4*)(A + (long)(k0 + kk) * M + m0 + mm);
                ra1 = *(const float4*)(A + (long)(k0 + kk + 8) * M + m0 + mm);
            } else {
                int mr = t >> 2, kv = (t & 3) << 2;
                ra0 = *(const float4*)(A + (long)(m0 + mr) * K + k0 + kv);
                ra1 = *(const float4*)(A + (long)(m0 + mr + 64) * K + k0 + kv);
            }
            if (!BNK) {
                int kk = t >> 4, nv = (t & 15) << 2;
                rb0 = *(const float4*)(B + (long)(k0 + kk) * N + n0 + nv);
            } else {
                int nr = t >> 2, kv = (t & 3) << 2;
                rb0 = *(const float4*)(B + (long)(n0 + nr) * K + k0 + kv);
            }
        }
#pragma unroll
        for (int kk = 0; kk < 16; kk++) {
            const ulonglong2 a01 = *(const ulonglong2*)&As[kk][tm << 3];
            const ulonglong2 a23 = *(const ulonglong2*)&As[kk][(tm << 3) + 4];
            const float4 bv = *(const float4*)&Bs[kk][tn << 2];
            u64 b0 = dup2(bv.x), b1 = dup2(bv.y), b2 = dup2(bv.z), b3 = dup2(bv.w);
            fma2(acc[0][0], a01.x, b0); fma2(acc[0][1], a01.x, b1);
            fma2(acc[0][2], a01.x, b2); fma2(acc[0][3], a01.x, b3);
            fma2(acc[1][0], a01.y, b0); fma2(acc[1][1], a01.y, b1);
            fma2(acc[1][2], a01.y, b2); fma2(acc[1][3], a01.y, b3);
            fma2(acc[2][0], a23.x, b0); fma2(acc[2][1], a23.x, b1);
            fma2(acc[2][2], a23.x, b2); fma2(acc[2][3], a23.x, b3);
            fma2(acc[3][0], a23.y, b0); fma2(acc[3][1], a23.y, b1);
            fma2(acc[3][2], a23.y, b2); fma2(acc[3][3], a23.y, b3);
        }
    }
    float sc = 1.f, gm = 0.f;
    if (EPI == 1) sc = 1.f / (g_sig[0] * g_sig[1]);
    else if (EPI == 2) sc = 1.f / g_sig[2];
    else if (EPI == 3) gm = gma[0] / g_sig[3];
#pragma unroll
    for (int p = 0; p < 4; p++) {
        float va[4], vb[4];
#pragma unroll
        for (int j = 0; j < 4; j++) {
            float2 u = up2(acc[p][j]);
            va[j] = u.x; vb[j] = u.y;
        }
#pragma unroll
        for (int h = 0; h < 2; h++) {
            const float* r = h ? vb : va;
            int m = m0 + (tm << 3) + 2 * p + h;
            long off = (long)m * N + n0 + (tn << 2);
            float4 v;
            if (EPI == 3) {
                float4 s4 = *(const float4*)(aux + (long)bz * sAux + off);
                v.x = 2.f * s4.x + gm * r[0];
                v.y = 2.f * s4.y + gm * r[1];
                v.z = 2.f * s4.z + gm * r[2];
                v.w = 2.f * s4.w + gm * r[3];
            } else {
                v.x = r[0] * sc; v.y = r[1] * sc;
                v.z = r[2] * sc; v.w = r[3] * sc;
            }
            *(float4*)(C + off) = v;
        }
    }
}

// ---------------- trace-normalized squaring: C = (A/t)^2 ----------------
__global__ void __launch_bounds__(256) k_sq(int srcbuf, int step, int mpair) {
    const int j = (mpair ? 2 : 0) + blockIdx.z;
    const int m = mpair ? 512 : 128;
    const float* __restrict__ A = &g_gram[srcbuf][j * 262144];
    float* __restrict__ C = &g_gram[srcbuf ^ 1][j * 262144];
    const float inv = 1.0f / g_tr[step - 1][j];
    const int t = threadIdx.x;
    const int m0 = blockIdx.y * 128, n0 = blockIdx.x * 64;
    __shared__ float As[16][132];
    __shared__ float Bs[16][68];
    const int tm = t >> 4, tn = t & 15;
    u64 acc[4][4];
#pragma unroll
    for (int i = 0; i < 4; i++)
#pragma unroll
        for (int j2 = 0; j2 < 4; j2++) acc[i][j2] = 0ull;
    const int nk = m >> 4;
    const int mr = t >> 2, kv = (t & 3) << 2;
    const int kkb = t >> 4, nv = (t & 15) << 2;
    float4 ra0 = *(const float4*)(A + (long)(m0 + mr) * m + kv);
    float4 ra1 = *(const float4*)(A + (long)(m0 + mr + 64) * m + kv);
    float4 rb0 = *(const float4*)(A + (long)kkb * m + n0 + nv);
    for (int kc = 0; kc < nk; kc++) {
        if (kc) __syncthreads();
        As[kv + 0][mr] = ra0.x; As[kv + 1][mr] = ra0.y;
        As[kv + 2][mr] = ra0.z; As[kv + 3][mr] = ra0.w;
        As[kv + 0][mr + 64] = ra1.x; As[kv + 1][mr + 64] = ra1.y;
        As[kv + 2][mr + 64] = ra1.z; As[kv + 3][mr + 64] = ra1.w;
        *(float4*)&Bs[kkb][nv] = rb0;
        __syncthreads();
        if (kc + 1 < nk) {
            int k0 = (kc + 1) << 4;
            ra0 = *(const float4*)(A + (long)(m0 + mr) * m + k0 + kv);
            ra1 = *(const float4*)(A + (long)(m0 + mr + 64) * m + k0 + kv);
            rb0 = *(const float4*)(A + (long)(k0 + kkb) * m + n0 + nv);
        }
#pragma unroll
        for (int kk = 0; kk < 16; kk++) {
            const ulonglong2 a01 = *(const ulonglong2*)&As[kk][tm << 3];
            const ulonglong2 a23 = *(const ulonglong2*)&As[kk][(tm << 3) + 4];
            const float4 bv = *(const float4*)&Bs[kk][tn << 2];
            u64 b0 = dup2(bv.x), b1 = dup2(bv.y), b2 = dup2(bv.z), b3 = dup2(bv.w);
            fma2(acc[0][0], a01.x, b0); fma2(acc[0][1], a01.x, b1);
            fma2(acc[0][2], a01.x, b2); fma2(acc[0][3], a01.x, b3);
            fma2(acc[1][0], a01.y, b0); fma2(acc[1][1], a01.y, b1);
            fma2(acc[1][2], a01.y, b2); fma2(acc[1][3], a01.y, b3);
            fma2(acc[2][0], a23.x, b0); fma2(acc[2][1], a23.x, b1);
            fma2(acc[2][2], a23.x, b2); fma2(acc[2][3], a23.x, b3);
            fma2(acc[3][0], a23.y, b0); fma2(acc[3][1], a23.y, b1);
            fma2(acc[3][2], a23.y, b2); fma2(acc[3][3], a23.y, b3);
        }
    }
    float s2 = inv * inv;
#pragma unroll
    for (int p = 0; p < 4; p++) {
        float2 u0 = up2(acc[p][0]), u1 = up2(acc[p][1]),
               u2 = up2(acc[p][2]), u3 = up2(acc[p][3]);
        long offA = (long)(m0 + (tm << 3) + 2 * p) * m + n0 + (tn << 2);
        float4 v;
        v.x = u0.x * s2; v.y = u1.x * s2; v.z = u2.x * s2; v.w = u3.x * s2;
        *(float4*)(C + offA) = v;
        v.x = u0.y * s2; v.y = u1.y * s2; v.z = u2.y * s2; v.w = u3.y * s2;
        *(float4*)(C + offA + m) = v;
    }
}

__global__ void k_trace(int step, int srcbuf) {
    int j = blockIdx.x;
    int m = (j < 2) ? 128 : 512;
    const float* A = &g_gram[srcbuf][j * 262144];
    __shared__ float red[512];
    float s = 0.f;
    for (int i = threadIdx.x; i < m; i += 512) s += A[(long)i * m + i];
    red[threadIdx.x] = s;
    __syncthreads();
    for (int o = 256; o > 0; o >>= 1) {
        if (threadIdx.x < o) red[threadIdx.x] += red[threadIdx.x + o];
        __syncthreads();
    }
    if (threadIdx.x == 0) g_tr[step][j] = red[0];
}

__global__ void k_sigfinal(int K) {
    int j = threadIdx.x;
    if (j >= 4) return;
    double la = 0.0, p = 1.0;
    for (int k = 0; k < K; k++) { la += log((double)g_tr[k][j]) * p; p *= 0.5; }
    la += log((double)g_tr[K][j]) * p;
    g_sig[j] = (float)exp(0.5 * la);
}

// ---------------- 2x2 maxpool over (c,w) + flat reshape ----------------
__global__ void k_pool(int which) {
    int C2 = which ? 256 : 64;
    int rowbase = which ? 256 : 128;
    float* out = which ? g_gr : g_phir;
    int total = BATCH * C2 * 1024;
    int i = blockIdx.x * 256 + threadIdx.x;
    if (i >= total) return;
    int w2 = i & 1023;
    int c2 = (i >> 10) % C2;
    int b = i / (C2 << 10);
    const float* P = &g_proj[((long)b * 768 + rowbase + 2 * c2) * WID + 2 * w2];
    float v = fmaxf(fmaxf(P[0], P[1]), fmaxf(P[WID], P[WID + 1]));
    out[(long)b * ((long)C2 << 10) + c2 * 1024 + w2] = v;
}

// ---------------- row softmax over 512 ----------------
__global__ void k_softmax() {
    int row = blockIdx.x * 8 + (threadIdx.x >> 5);
    int lane = threadIdx.x & 31;
    float* p = g_attn + (long)row * 512;
    float v[16];
#pragma unroll
    for (int r = 0; r < 4; r++)
        *(float4*)&v[r * 4] = *(const float4*)&p[r * 128 + lane * 4];
    float mx = v[0];
#pragma unroll
    for (int i = 1; i < 16; i++) mx = fmaxf(mx, v[i]);
#pragma unroll
    for (int o = 16; o > 0; o >>= 1) mx = fmaxf(mx, __shfl_xor_sync(0xffffffffu, mx, o));
    float s = 0.f;
#pragma unroll
    for (int i = 0; i < 16; i++) { v[i] = __expf(v[i] - mx); s += v[i]; }
#pragma unroll
    for (int o = 16; o > 0; o >>= 1) s += __shfl_xor_sync(0xffffffffu, s, o);
    float inv = 1.f / s;
#pragma unroll
    for (int i = 0; i < 16; i++) v[i] *= inv;
#pragma unroll
    for (int r = 0; r < 4; r++)
        *(float4*)&p[r * 128 + lane * 4] = *(const float4*)&v[r * 4];
}

// -------- transpose + hi/lo split: g_x [b][ch][w] -> Xt1 [b*2048+w][ch] ------
__global__ void k_tcvt(const float* __restrict__ X,
                       __nv_bfloat16* __restrict__ Xh, __nv_bfloat16* __restrict__ Xl) {
    __shared__ float tile[32][33];
    int b = blockIdx.z, w0 = blockIdx.x * 32, c0 = blockIdx.y * 32;
    int tx = threadIdx.x, ty = threadIdx.y;   // 32 x 8
#pragma unroll
    for (int i = 0; i < 4; i++)
        tile[ty + i * 8][tx] = X[((long)b * 1024 + c0 + ty + i * 8) * 2048 + w0 + tx];
    __syncthreads();
#pragma unroll
    for (int i = 0; i < 4; i++) {
        float v = tile[tx][ty + i * 8];
        long o = ((long)(b * 2048 + w0 + ty + i * 8)) * 1024 + c0 + tx;
        __nv_bfloat16 h = __float2bfloat16(v);
        Xh[o] = h;
        Xl[o] = __float2bfloat16(v - __bfloat162float(h));
    }
}

// -------- weight repack: w[oc][ic][k] -> W[k][oc][ic] hi/lo ------------------
__global__ void k_wprep(const float* __restrict__ w,
                        __nv_bfloat16* __restrict__ Wh, __nv_bfloat16* __restrict__ Wl,
                        int OCt, int ICt) {
    long n = (long)OCt * ICt * 3;
    long i = (long)blockIdx.x * 256 + threadIdx.x;
    if (i >= n) return;
    int k = (int)(i / ((long)OCt * ICt));
    long rem = i - (long)k * OCt * ICt;
    int oc = (int)(rem / ICt), ic = (int)(rem % ICt);
    float v = w[((long)oc * ICt + ic) * 3 + k];
    __nv_bfloat16 h = __float2bfloat16(v);
    Wh[i] = h;
    Wl[i] = __float2bfloat16(v - __bfloat162float(h));
}

// -------- conv1d k=3 'same' via mma.sync HMMA, bf16x3 split ------------------
// CTA tile: 128 (w) x 128 (oc). 8 warps, each 64x32 (4 m16 x 4 n8).
// K-chunks of 32 ic; 3 kshifts. cp.async double-buffered smem:
// per stage: Ah(10240) Al(10240) Bh(10240) Bl(10240), row stride 80B.
template <int FINAL>
__global__ void __launch_bounds__(256) k_convhmma(
    const __nv_bfloat16* __restrict__ Xh, const __nv_bfloat16* __restrict__ Xl,
    const __nv_bfloat16* __restrict__ Wh, const __nv_bfloat16* __restrict__ Wl,
    const float* __restrict__ bias, int IC, int OCt,
    __nv_bfloat16* __restrict__ Yh, __nv_bfloat16* __restrict__ Yl,
    float* __restrict__ Yt) {
    extern __shared__ char dsm[];
    const int t = threadIdx.x, lane = t & 31, wid = t >> 5;
    const int oc0 = blockIdx.x * 128;
    const int Mtile = blockIdx.y;
    const int bb = Mtile >> 4, w0 = (Mtile & 15) << 7;
    const int wm = wid >> 2, wn = wid & 3;
    const u32 smb = smem_u32(dsm);
    const int nic = IC >> 5;
    const int C = 3 * nic;

    float acc[4][4][4];
#pragma unroll
    for (int a = 0; a < 4; a++)
#pragma unroll
        for (int b = 0; b < 4; b++)
#pragma unroll
            for (int c = 0; c < 4; c++) acc[a][b][c] = 0.f;

    auto load_stage = [&](int c) {
        const int kshift = c / nic;
        const int icc = (c - kshift * nic) << 5;
        const u32 sb = smb + (u32)(c & 1) * 40960u;
#pragma unroll
        for (int i = 0; i < 2; i++) {
            int s = t + i * 256;
            int row = s >> 2, segc = (s & 3) << 4;
            int wl = w0 + row + kshift - 1;
            u32 ok = (wl >= 0 && wl < 2048) ? 16u : 0u;
            int wcl = wl < 0 ? 0 : (wl > 2047 ? 2047 : wl);
            long ga = ((long)(bb * 2048 + wcl) * IC + icc) * 2 + segc;
            u32 soA = sb + row * 80 + segc;
            cpasync(soA, (const char*)Xh + ga, ok);
            cpasync(soA + 10240, (const char*)Xl + ga, ok);
            long gb = ((long)(kshift * OCt + oc0 + row) * IC + icc) * 2 + segc;
            u32 soB = sb + 20480 + row * 80 + segc;
            cpasync(soB, (const char*)Wh + gb, 16u);
            cpasync(soB + 10240, (const char*)Wl + gb, 16u);
        }
        CP_COMMIT();
    };

    load_stage(0);
    if (C > 1) load_stage(1);

    for (int c = 0; c < C; c++) {
        if (c + 1 < C) asm volatile("cp.async.wait_group 1;" ::: "memory");
        else           asm volatile("cp.async.wait_group 0;" ::: "memory");
        __syncthreads();
        const u32 sb = smb + (u32)(c & 1) * 40960u;
        const u32 aB = sb + (u32)(wm * 64 + (lane & 15)) * 80 + (u32)((lane >> 4) << 4);
        const u32 bB = sb + 20480u
                       + (u32)(wn * 32 + (lane & 7) + ((lane >> 4) << 3)) * 80
                       + (u32)(((lane >> 3) & 1) << 4);
#pragma unroll
        for (int ks = 0; ks < 2; ks++) {
            u32 AH[16], AL2[16], BH[8], BL[8];
#pragma unroll
            for (int mt = 0; mt < 4; mt++) {
                u32 a = aB + ks * 32 + mt * (16 * 80);
                LDM4(AH + mt * 4, a);
                LDM4(AL2 + mt * 4, a + 10240);
            }
#pragma unroll
            for (int np = 0; np < 2; np++) {
                u32 b = bB + ks * 32 + np * (16 * 80);
                LDM4(BH + np * 4, b);
                LDM4(BL + np * 4, b + 10240);
            }
#pragma unroll
            for (int mt = 0; mt < 4; mt++)
#pragma unroll
                for (int nt = 0; nt < 4; nt++) {
                    const int bi = (nt >> 1) * 4 + (nt & 1) * 2;
                    MMA(acc[mt][nt], AH + mt * 4, BH[bi], BH[bi + 1]);
                    MMA(acc[mt][nt], AH + mt * 4, BL[bi], BL[bi + 1]);
                    MMA(acc[mt][nt], AL2 + mt * 4, BH[bi], BH[bi + 1]);
                }
        }
        __syncthreads();
        if (c + 2 < C) load_stage(c + 2);
    }

    // epilogue
    const int mrb = wm * 64 + (lane >> 2);
#pragma unroll
    for (int mt = 0; mt < 4; mt++) {
        const int mr = mrb + mt * 16;
        const long grow = (long)Mtile * 128 + mr;
#pragma unroll
        for (int nt = 0; nt < 4; nt++) {
            const int oc = oc0 + wn * 32 + nt * 8 + ((lane & 3) << 1);
            const float b0v = __ldg(bias + oc), b1v = __ldg(bias + oc + 1);
            float v00 = fmaxf(acc[mt][nt][0] + b0v, 0.f);
            float v01 = fmaxf(acc[mt][nt][1] + b1v, 0.f);
            float v10 = fmaxf(acc[mt][nt][2] + b0v, 0.f);
            float v11 = fmaxf(acc[mt][nt][3] + b1v, 0.f);
            if (FINAL) {
                *(float2*)(Yt + grow * OCt + oc) = make_float2(v00, v01);
                *(float2*)(Yt + (grow + 8) * OCt + oc) = make_float2(v10, v11);
            } else {
                __nv_bfloat16 h0 = __float2bfloat16(v00);
                __nv_bfloat16 h1 = __float2bfloat16(v01);
                __nv_bfloat16 h2 = __float2bfloat16(v10);
                __nv_bfloat16 h3 = __float2bfloat16(v11);
                u32 hp0 = (u32)__bfloat16_as_ushort(h0) |
                          ((u32)__bfloat16_as_ushort(h1) << 16);
                u32 hp1 = (u32)__bfloat16_as_ushort(h2) |
                          ((u32)__bfloat16_as_ushort(h3) << 16);
                __nv_bfloat16 l0 = __float2bfloat16(v00 - __bfloat162float(h0));
                __nv_bfloat16 l1 = __float2bfloat16(v01 - __bfloat162float(h1));
                __nv_bfloat16 l2 = __float2bfloat16(v10 - __bfloat162float(h2));
                __nv_bfloat16 l3 = __float2bfloat16(v11 - __bfloat162float(h3));
                u32 lp0 = (u32)__bfloat16_as_ushort(l0) |
                          ((u32)__bfloat16_as_ushort(l1) << 16);
                u32 lp1 = (u32)__bfloat16_as_ushort(l2) |
                          ((u32)__bfloat16_as_ushort(l3) << 16);
                *(u32*)(Yh + grow * OCt + oc) = hp0;
                *(u32*)(Yh + (grow + 8) * OCt + oc) = hp1;
                *(u32*)(Yl + grow * OCt + oc) = lp0;
                *(u32*)(Yl + (grow + 8) * OCt + oc) = lp1;
            }
        }
    }
}

// -------- final transpose + residual: out[b][oc][w] = T[b*2048+w][oc]+src ----
__global__ void k_fin(const float* __restrict__ T, const float* __restrict__ src,
                      float* __restrict__ out) {
    __shared__ float tile[32][33];
    int b = blockIdx.z, w0 = blockIdx.x * 32, c0 = blockIdx.y * 32;
    int tx = threadIdx.x, ty = threadIdx.y;   // 32 x 8
#pragma unroll
    for (int i = 0; i < 4; i++)
        tile[ty + i * 8][tx] = T[((long)(b * 2048 + w0 + ty + i * 8)) * 1024 + c0 + tx];
    __syncthreads();
#pragma unroll
    for (int i = 0; i < 4; i++) {
        long o = ((long)(b * 1024 + c0 + ty + i * 8)) * 2048 + w0 + tx;
        out[o] = tile[tx][ty + i * 8] + src[o];
    }
}

// ---------------- launch ----------------
extern "C" void kernel_launch(void* const* d_in, const int* in_sizes, int n_in,
                              void* d_out, int out_size) {
    const float* src     = (const float*)d_in[0];
    const float* w_theta = (const float*)d_in[1];
    const float* w_phi   = (const float*)d_in[2];
    const float* w_g     = (const float*)d_in[3];
    const float* w_o     = (const float*)d_in[4];
    const float* gamma   = (const float*)d_in[5];
    const float* w_c1 = (const float*)d_in[6];  const float* b_c1 = (const float*)d_in[7];
    const float* w_c2 = (const float*)d_in[8];  const float* b_c2 = (const float*)d_in[9];
    const float* w_c3 = (const float*)d_in[10]; const float* b_c3 = (const float*)d_in[11];
    const float* w_c4 = (const float*)d_in[12]; const float* b_c4 = (const float*)d_in[13];
    float* out = (float*)d_out;

    static float *p_wpack = nullptr, *p_proj, *p_phir, *p_gr, *p_attn, *p_ag,
                 *p_x, *p_gram;
    static __nv_bfloat16 *x1h, *x1l, *x2h, *x2l, *x3h, *x3l, *x4h, *x4l;
    static __nv_bfloat16 *w1h, *w1l, *w2h, *w2l, *w3h, *w3l, *w4h, *w4l;
    if (!p_wpack) {
        cudaGetSymbolAddress((void**)&p_wpack, g_wpack);
        cudaGetSymbolAddress((void**)&p_proj,  g_proj);
        cudaGetSymbolAddress((void**)&p_phir,  g_phir);
        cudaGetSymbolAddress((void**)&p_gr,    g_gr);
        cudaGetSymbolAddress((void**)&p_attn,  g_attn);
        cudaGetSymbolAddress((void**)&p_ag,    g_ag);
        cudaGetSymbolAddress((void**)&p_x,     g_x);
        cudaGetSymbolAddress((void**)&p_gram,  g_gram);
        cudaGetSymbolAddress((void**)&x1h, g_xt1h); cudaGetSymbolAddress((void**)&x1l, g_xt1l);
        cudaGetSymbolAddress((void**)&x2h, g_xt2h); cudaGetSymbolAddress((void**)&x2l, g_xt2l);
        cudaGetSymbolAddress((void**)&x3h, g_xt3h); cudaGetSymbolAddress((void**)&x3l, g_xt3l);
        cudaGetSymbolAddress((void**)&x4h, g_xt4h); cudaGetSymbolAddress((void**)&x4l, g_xt4l);
        cudaGetSymbolAddress((void**)&w1h, g_w1h);  cudaGetSymbolAddress((void**)&w1l, g_w1l);
        cudaGetSymbolAddress((void**)&w2h, g_w2h);  cudaGetSymbolAddress((void**)&w2l, g_w2l);
        cudaGetSymbolAddress((void**)&w3h, g_w3h);  cudaGetSymbolAddress((void**)&w3l, g_w3l);
        cudaGetSymbolAddress((void**)&w4h, g_w4h);  cudaGetSymbolAddress((void**)&w4l, g_w4l);
        cudaFuncSetAttribute(k_convhmma<0>,
                             cudaFuncAttributeMaxDynamicSharedMemorySize, 81920);
        cudaFuncSetAttribute(k_convhmma<1>,
                             cudaFuncAttributeMaxDynamicSharedMemorySize, 81920);
    }

    // 1) projections
    k_pack<<<3072, 256>>>(w_theta, w_phi, w_g);
    k_gemm<0, 0, 0><<<dim3(32, 6, 4), 256>>>(p_wpack, src, p_proj,
        768, 2048, 1024, 0, 2097152, 1572864, nullptr, 0, nullptr);
    // 2) pools
    k_pool<<<1024, 256>>>(0);
    k_pool<<<4096, 256>>>(1);
    // 3) Gram matrices
    k_gemm<0, 1, 0><<<dim3(2, 1, 1), 256>>>(w_theta, w_theta, p_gram,
        128, 128, 1024, 0, 0, 0, nullptr, 0, nullptr);
    k_gemm<0, 1, 0><<<dim3(2, 1, 1), 256>>>(w_phi, w_phi, p_gram + 262144,
        128, 128, 1024, 0, 0, 0, nullptr, 0, nullptr);
    k_gemm<0, 1, 0><<<dim3(8, 4, 1), 256>>>(w_g, w_g, p_gram + 524288,
        512, 512, 1024, 0, 0, 0, nullptr, 0, nullptr);
    k_gemm<1, 0, 0><<<dim3(8, 4, 1), 256>>>(w_o, w_o, p_gram + 786432,
        512, 512, 1024, 0, 0, 0, nullptr, 0, nullptr);
    // 4) sigma chain
    k_trace<<<4, 512>>>(0, 0);
    for (int s = 1; s <= 10; s++) {
        k_sq<<<dim3(2, 1, 2), 256>>>((s - 1) & 1, s, 0);
        k_sq<<<dim3(8, 4, 2), 256>>>((s - 1) & 1, s, 1);
        k_trace<<<4, 512>>>(s, s & 1);
    }
    k_sigfinal<<<1, 4>>>(10);
    // 5) logits + softmax
    k_gemm<1, 0, 1><<<dim3(8, 16, 4), 256>>>(p_proj, p_phir, p_attn,
        2048, 512, 128, 1572864, 65536, 1048576, nullptr, 0, nullptr);
    k_softmax<<<1024, 256>>>();
    // 6) attn_g
    k_gemm<0, 1, 2><<<dim3(32, 4, 4), 256>>>(p_gr, p_attn, p_ag,
        512, 2048, 512, 262144, 1048576, 1048576, nullptr, 0, nullptr);
    // 7) x = 2*src + (gamma/sig_o) * (w_o @ attn_g)
    k_gemm<0, 0, 3><<<dim3(32, 8, 4), 256>>>(w_o, p_ag, p_x,
        1024, 2048, 512, 0, 1048576, 2097152, src, 2097152, gamma);
    // 8) conv FFN on HMMA (mma.sync), bf16x3
    k_tcvt<<<dim3(64, 32, 4), dim3(32, 8)>>>(p_x, x1h, x1l);
    k_wprep<<<6144, 256>>>(w_c1, w1h, w1l, 512, 1024);
    k_wprep<<<3072, 256>>>(w_c2, w2h, w2l, 512, 512);
    k_wprep<<<3072, 256>>>(w_c3, w3h, w3l, 512, 512);
    k_wprep<<<6144, 256>>>(w_c4, w4h, w4l, 1024, 512);
    k_convhmma<0><<<dim3(4, 64), 256, 81920>>>(x1h, x1l, w1h, w1l, b_c1,
        1024, 512, x2h, x2l, nullptr);
    k_convhmma<0><<<dim3(4, 64), 256, 81920>>>(x2h, x2l, w2h, w2l, b_c2,
        512, 512, x3h, x3l, nullptr);
    k_convhmma<0><<<dim3(4, 64), 256, 81920>>>(x3h, x3l, w3h, w3l, b_c3,
        512, 512, x4h, x4l, nullptr);
    k_convhmma<1><<<dim3(8, 64), 256, 81920>>>(x4h, x4l, w4h, w4l, b_c4,
        512, 1024, nullptr, nullptr, p_x);
    k_fin<<<dim3(64, 32, 4), dim3(32, 8)>>>(p_x, src, out);
    (void)in_sizes; (void)n_in; (void)out_size;
}

// round 17
// speedup vs baseline: 2.1542x; 1.1656x over previous
#include <cuda_runtime.h>
#include <cuda_bf16.h>
#include <math.h>

#define BATCH 4
#define CH    1024
#define WID   2048
#define OC    512

typedef unsigned long long u64;
typedef unsigned int u32;

__device__ __forceinline__ u64 dup2(float v) {
    u64 r; asm("mov.b64 %0,{%1,%1};" : "=l"(r) : "f"(v)); return r;
}
__device__ __forceinline__ void fma2(u64& c, u64 a, u64 b) {
    asm("fma.rn.f32x2 %0,%1,%2,%0;" : "+l"(c) : "l"(a), "l"(b));
}
__device__ __forceinline__ float2 up2(u64 v) {
    float2 f; asm("mov.b64 {%0,%1},%2;" : "=f"(f.x), "=f"(f.y) : "l"(v)); return f;
}
__device__ __forceinline__ u32 smem_u32(const void* p) {
    u32 a; asm("{ .reg .u64 t; cvta.to.shared.u64 t, %1; cvt.u32.u64 %0, t; }"
               : "=r"(a) : "l"(p));
    return a;
}
__device__ __forceinline__ void cpasync(u32 dst, const void* src, u32 sz) {
    asm volatile("cp.async.ca.shared.global [%0], [%1], 16, %2;"
                 :: "r"(dst), "l"(src), "r"(sz));
}
#define CP_COMMIT() asm volatile("cp.async.commit_group;" ::: "memory")
#define LDM4(r, addr)                                                        \
    asm volatile("ldmatrix.sync.aligned.m8n8.x4.shared.b16 {%0,%1,%2,%3}, [%4];" \
        : "=r"((r)[0]), "=r"((r)[1]), "=r"((r)[2]), "=r"((r)[3]) : "r"(addr))
#define MMA(d, a, b0, b1)                                                    \
    asm volatile("mma.sync.aligned.m16n8k16.row.col.f32.bf16.bf16.f32 "      \
        "{%0,%1,%2,%3}, {%4,%5,%6,%7}, {%8,%9}, {%0,%1,%2,%3};"              \
        : "+f"((d)[0]), "+f"((d)[1]), "+f"((d)[2]), "+f"((d)[3])             \
        : "r"((a)[0]), "r"((a)[1]), "r"((a)[2]), "r"((a)[3]), "r"(b0), "r"(b1))

// ---------------- scratch ----------------
__device__ float g_wpack[768 * 1024];
__device__ float g_proj[BATCH * 768 * WID];
__device__ float g_phir[BATCH * 128 * 512];
__device__ float g_attn[(long)BATCH * WID * 512];
__device__ float g_x[(long)BATCH * CH * WID];
__device__ float g_gram[2][4 * 512 * 512];
__device__ float g_tr[16][4];
__device__ float g_sig[4];
// bf16 hi/lo buffers (multi-purpose; lifetimes ordered in kernel_launch)
__device__ __nv_bfloat16 g_xt1h[8192L * 1024], g_xt1l[8192L * 1024]; // srcT, then xT(conv1 in)
__device__ __nv_bfloat16 g_xt2h[8192L * 512],  g_xt2l[8192L * 512];  // g_r, then conv2 in
__device__ __nv_bfloat16 g_xt3h[8192L * 512],  g_xt3l[8192L * 512];  // attn, then conv3 in
__device__ __nv_bfloat16 g_xt4h[8192L * 512],  g_xt4l[8192L * 512];  // agT, then conv4 in
__device__ __nv_bfloat16 g_w1h[3L * 512 * 1024], g_w1l[3L * 512 * 1024]; // wpack, then conv1 w
__device__ __nv_bfloat16 g_w2h[3L * 512 * 512],  g_w2l[3L * 512 * 512];  // w_o, then conv2 w
__device__ __nv_bfloat16 g_w3h[3L * 512 * 512],  g_w3l[3L * 512 * 512];
__device__ __nv_bfloat16 g_w4h[3L * 1024 * 512], g_w4l[3L * 1024 * 512];

// -------- pack theta|phi|g into [768,1024] bf16 hi/lo ------------------------
__global__ void k_packsplit(const float* __restrict__ wt, const float* __restrict__ wp,
                            const float* __restrict__ wg) {
    int i = blockIdx.x * 256 + threadIdx.x;
    if (i >= 768 * 1024) return;
    int r = i >> 10;
    float v = (r < 128) ? wt[i] : (r < 256) ? wp[i - 131072] : wg[i - 262144];
    __nv_bfloat16 h = __float2bfloat16(v);
    g_w1h[i] = h;
    g_w1l[i] = __float2bfloat16(v - __bfloat162float(h));
}

// -------- w_o [1024][512] -> bf16 hi/lo --------------------------------------
__global__ void k_wosplit(const float* __restrict__ w) {
    int i = blockIdx.x * 256 + threadIdx.x;
    if (i >= 1024 * 512) return;
    float v = w[i];
    __nv_bfloat16 h = __float2bfloat16(v);
    g_w2h[i] = h;
    g_w2l[i] = __float2bfloat16(v - __bfloat162float(h));
}

// ---------------- generic tiled SIMT GEMM (kept for gram/sigma/logits) -------
template <int AKM, int BNK, int EPI>
__global__ void __launch_bounds__(256) k_gemm(
    const float* __restrict__ A, const float* __restrict__ B, float* __restrict__ C,
    int M, int N, int K, long sA, long sB, long sC,
    const float* __restrict__ aux, long sAux, const float* __restrict__ gma) {
    const int t = threadIdx.x;
    const int bz = blockIdx.z;
    A += (long)bz * sA;  B += (long)bz * sB;  C += (long)bz * sC;
    const int m0 = blockIdx.y * 128, n0 = blockIdx.x * 64;
    __shared__ float As[16][132];
    __shared__ float Bs[16][68];
    const int tm = t >> 4, tn = t & 15;
    u64 acc[4][4];
#pragma unroll
    for (int i = 0; i < 4; i++)
#pragma unroll
        for (int j = 0; j < 4; j++) acc[i][j] = 0ull;

    float4 ra0, ra1, rb0;
    const int nk = K >> 4;
    {
        if (AKM) {
            int kk = t >> 5, mm = (t & 31) << 2;
            ra0 = *(const float4*)(A + (long)kk * M + m0 + mm);
            ra1 = *(const float4*)(A + (long)(kk + 8) * M + m0 + mm);
        } else {
            int mr = t >> 2, kv = (t & 3) << 2;
            ra0 = *(const float4*)(A + (long)(m0 + mr) * K + kv);
            ra1 = *(const float4*)(A + (long)(m0 + mr + 64) * K + kv);
        }
        if (!BNK) {
            int kk = t >> 4, nv = (t & 15) << 2;
            rb0 = *(const float4*)(B + (long)kk * N + n0 + nv);
        } else {
            int nr = t >> 2, kv = (t & 3) << 2;
            rb0 = *(const float4*)(B + (long)(n0 + nr) * K + kv);
        }
    }
    for (int kc = 0; kc < nk; kc++) {
        if (kc) __syncthreads();
        if (AKM) {
            int kk = t >> 5, mm = (t & 31) << 2;
            *(float4*)&As[kk][mm] = ra0;
            *(float4*)&As[kk + 8][mm] = ra1;
        } else {
            int mr = t >> 2, kv = (t & 3) << 2;
            As[kv + 0][mr] = ra0.x; As[kv + 1][mr] = ra0.y;
            As[kv + 2][mr] = ra0.z; As[kv + 3][mr] = ra0.w;
            As[kv + 0][mr + 64] = ra1.x; As[kv + 1][mr + 64] = ra1.y;
            As[kv + 2][mr + 64] = ra1.z; As[kv + 3][mr + 64] = ra1.w;
        }
        if (!BNK) {
            int kk = t >> 4, nv = (t & 15) << 2;
            *(float4*)&Bs[kk][nv] = rb0;
        } else {
            int nr = t >> 2, kv = (t & 3) << 2;
            Bs[kv + 0][nr] = rb0.x; Bs[kv + 1][nr] = rb0.y;
            Bs[kv + 2][nr] = rb0.z; Bs[kv + 3][nr] = rb0.w;
        }
        __syncthreads();
        if (kc + 1 < nk) {
            int k0 = (kc + 1) << 4;
            if (AKM) {
                int kk = t >> 5, mm = (t & 31) << 2;
                ra0 = *(const float4*)(A + (long)(k0 + kk) * M + m0 + mm);
                ra1 = *(const float4*)(A + (long)(k0 + kk + 8) * M + m0 + mm);
            } else {
                int mr = t >> 2, kv = (t & 3) << 2;
                ra0 = *(const float4*)(A + (long)(m0 + mr) * K + k0 + kv);
                ra1 = *(const float4*)(A + (long)(m0 + mr + 64) * K + k0 + kv);
            }
            if (!BNK) {
                int kk = t >> 4, nv = (t & 15) << 2;
                rb0 = *(const float4*)(B + (long)(k0 + kk) * N + n0 + nv);
            } else {
                int nr = t >> 2, kv = (t & 3) << 2;
                rb0 = *(const float4*)(B + (long)(n0 + nr) * K + k0 + kv);
            }
        }
#pragma unroll
        for (int kk = 0; kk < 16; kk++) {
            const ulonglong2 a01 = *(const ulonglong2*)&As[kk][tm << 3];
            const ulonglong2 a23 = *(const ulonglong2*)&As[kk][(tm << 3) + 4];
            const float4 bv = *(const float4*)&Bs[kk][tn << 2];
            u64 b0 = dup2(bv.x), b1 = dup2(bv.y), b2 = dup2(bv.z), b3 = dup2(bv.w);
            fma2(acc[0][0], a01.x, b0); fma2(acc[0][1], a01.x, b1);
            fma2(acc[0][2], a01.x, b2); fma2(acc[0][3], a01.x, b3);
            fma2(acc[1][0], a01.y, b0); fma2(acc[1][1], a01.y, b1);
            fma2(acc[1][2], a01.y, b2); fma2(acc[1][3], a01.y, b3);
            fma2(acc[2][0], a23.x, b0); fma2(acc[2][1], a23.x, b1);
            fma2(acc[2][2], a23.x, b2); fma2(acc[2][3], a23.x, b3);
            fma2(acc[3][0], a23.y, b0); fma2(acc[3][1], a23.y, b1);
            fma2(acc[3][2], a23.y, b2); fma2(acc[3][3], a23.y, b3);
        }
    }
    float sc = 1.f;
    if (EPI == 1) sc = 1.f / (g_sig[0] * g_sig[1]);
#pragma unroll
    for (int p = 0; p < 4; p++) {
        float va[4], vb[4];
#pragma unroll
        for (int j = 0; j < 4; j++) {
            float2 u = up2(acc[p][j]);
            va[j] = u.x; vb[j] = u.y;
        }
#pragma unroll
        for (int h = 0; h < 2; h++) {
            const float* r = h ? vb : va;
            int m = m0 + (tm << 3) + 2 * p + h;
            long off = (long)m * N + n0 + (tn << 2);
            float4 v;
            v.x = r[0] * sc; v.y = r[1] * sc;
            v.z = r[2] * sc; v.w = r[3] * sc;
            *(float4*)(C + off) = v;
        }
    }
    (void)aux; (void)sAux; (void)gma;
}

// ---------------- trace-normalized squaring: C = (A/t)^2 ----------------
__global__ void __launch_bounds__(256) k_sq(int srcbuf, int step, int mpair) {
    const int j = (mpair ? 2 : 0) + blockIdx.z;
    const int m = mpair ? 512 : 128;
    const float* __restrict__ A = &g_gram[srcbuf][j * 262144];
    float* __restrict__ C = &g_gram[srcbuf ^ 1][j * 262144];
    const float inv = 1.0f / g_tr[step - 1][j];
    const int t = threadIdx.x;
    const int m0 = blockIdx.y * 128, n0 = blockIdx.x * 64;
    __shared__ float As[16][132];
    __shared__ float Bs[16][68];
    const int tm = t >> 4, tn = t & 15;
    u64 acc[4][4];
#pragma unroll
    for (int i = 0; i < 4; i++)
#pragma unroll
        for (int j2 = 0; j2 < 4; j2++) acc[i][j2] = 0ull;
    const int nk = m >> 4;
    const int mr = t >> 2, kv = (t & 3) << 2;
    const int kkb = t >> 4, nv = (t & 15) << 2;
    float4 ra0 = *(const float4*)(A + (long)(m0 + mr) * m + kv);
    float4 ra1 = *(const float4*)(A + (long)(m0 + mr + 64) * m + kv);
    float4 rb0 = *(const float4*)(A + (long)kkb * m + n0 + nv);
    for (int kc = 0; kc < nk; kc++) {
        if (kc) __syncthreads();
        As[kv + 0][mr] = ra0.x; As[kv + 1][mr] = ra0.y;
        As[kv + 2][mr] = ra0.z; As[kv + 3][mr] = ra0.w;
        As[kv + 0][mr + 64] = ra1.x; As[kv + 1][mr + 64] = ra1.y;
        As[kv + 2][mr + 64] = ra1.z; As[kv + 3][mr + 64] = ra1.w;
        *(float4*)&Bs[kkb][nv] = rb0;
        __syncthreads();
        if (kc + 1 < nk) {
            int k0 = (kc + 1) << 4;
            ra0 = *(const float4*)(A + (long)(m0 + mr) * m + k0 + kv);
            ra1 = *(const float4*)(A + (long)(m0 + mr + 64) * m + k0 + kv);
            rb0 = *(const float4*)(A + (long)(k0 + kkb) * m + n0 + nv);
        }
#pragma unroll
        for (int kk = 0; kk < 16; kk++) {
            const ulonglong2 a01 = *(const ulonglong2*)&As[kk][tm << 3];
            const ulonglong2 a23 = *(const ulonglong2*)&As[kk][(tm << 3) + 4];
            const float4 bv = *(const float4*)&Bs[kk][tn << 2];
            u64 b0 = dup2(bv.x), b1 = dup2(bv.y), b2 = dup2(bv.z), b3 = dup2(bv.w);
            fma2(acc[0][0], a01.x, b0); fma2(acc[0][1], a01.x, b1);
            fma2(acc[0][2], a01.x, b2); fma2(acc[0][3], a01.x, b3);
            fma2(acc[1][0], a01.y, b0); fma2(acc[1][1], a01.y, b1);
            fma2(acc[1][2], a01.y, b2); fma2(acc[1][3], a01.y, b3);
            fma2(acc[2][0], a23.x, b0); fma2(acc[2][1], a23.x, b1);
            fma2(acc[2][2], a23.x, b2); fma2(acc[2][3], a23.x, b3);
            fma2(acc[3][0], a23.y, b0); fma2(acc[3][1], a23.y, b1);
            fma2(acc[3][2], a23.y, b2); fma2(acc[3][3], a23.y, b3);
        }
    }
    float s2 = inv * inv;
#pragma unroll
    for (int p = 0; p < 4; p++) {
        float2 u0 = up2(acc[p][0]), u1 = up2(acc[p][1]),
               u2 = up2(acc[p][2]), u3 = up2(acc[p][3]);
        long offA = (long)(m0 + (tm << 3) + 2 * p) * m + n0 + (tn << 2);
        float4 v;
        v.x = u0.x * s2; v.y = u1.x * s2; v.z = u2.x * s2; v.w = u3.x * s2;
        *(float4*)(C + offA) = v;
        v.x = u0.y * s2; v.y = u1.y * s2; v.z = u2.y * s2; v.w = u3.y * s2;
        *(float4*)(C + offA + m) = v;
    }
}

__global__ void k_trace(int step, int srcbuf) {
    int j = blockIdx.x;
    int m = (j < 2) ? 128 : 512;
    const float* A = &g_gram[srcbuf][j * 262144];
    __shared__ float red[512];
    float s = 0.f;
    for (int i = threadIdx.x; i < m; i += 512) s += A[(long)i * m + i];
    red[threadIdx.x] = s;
    __syncthreads();
    for (int o = 256; o > 0; o >>= 1) {
        if (threadIdx.x < o) red[threadIdx.x] += red[threadIdx.x + o];
        __syncthreads();
    }
    if (threadIdx.x == 0) g_tr[step][j] = red[0];
}

__global__ void k_sigfinal(int K) {
    int j = threadIdx.x;
    if (j >= 4) return;
    double la = 0.0, p = 1.0;
    for (int k = 0; k < K; k++) { la += log((double)g_tr[k][j]) * p; p *= 0.5; }
    la += log((double)g_tr[K][j]) * p;
    g_sig[j] = (float)exp(0.5 * la);
}

// ------ 2x2 maxpool + flat reshape; which=1 emits bf16 hi/lo (g_r) ----------
__global__ void k_pool(int which) {
    int C2 = which ? 256 : 64;
    int rowbase = which ? 256 : 128;
    int total = BATCH * C2 * 1024;
    int i = blockIdx.x * 256 + threadIdx.x;
    if (i >= total) return;
    int w2 = i & 1023;
    int c2 = (i >> 10) % C2;
    int b = i / (C2 << 10);
    const float* P = &g_proj[((long)b * 768 + rowbase + 2 * c2) * WID + 2 * w2];
    float v = fmaxf(fmaxf(P[0], P[1]), fmaxf(P[WID], P[WID + 1]));
    long o = (long)b * ((long)C2 << 10) + c2 * 1024 + w2;
    if (which) {
        __nv_bfloat16 h = __float2bfloat16(v);
        g_xt2h[o] = h;
        g_xt2l[o] = __float2bfloat16(v - __bfloat162float(h));
    } else {
        g_phir[o] = v;
    }
}

// ------- row softmax over 512, emits bf16 hi/lo into g_xt3h/l ---------------
__global__ void k_softmax() {
    int row = blockIdx.x * 8 + (threadIdx.x >> 5);
    int lane = threadIdx.x & 31;
    const float* p = g_attn + (long)row * 512;
    float v[16];
#pragma unroll
    for (int r = 0; r < 4; r++)
        *(float4*)&v[r * 4] = *(const float4*)&p[r * 128 + lane * 4];
    float mx = v[0];
#pragma unroll
    for (int i = 1; i < 16; i++) mx = fmaxf(mx, v[i]);
#pragma unroll
    for (int o = 16; o > 0; o >>= 1) mx = fmaxf(mx, __shfl_xor_sync(0xffffffffu, mx, o));
    float s = 0.f;
#pragma unroll
    for (int i = 0; i < 16; i++) { v[i] = __expf(v[i] - mx); s += v[i]; }
#pragma unroll
    for (int o = 16; o > 0; o >>= 1) s += __shfl_xor_sync(0xffffffffu, s, o);
    float inv = 1.f / s;
#pragma unroll
    for (int i = 0; i < 16; i++) v[i] *= inv;
#pragma unroll
    for (int r = 0; r < 4; r++) {
        int base = r * 128 + lane * 4;
        u32 hp[2], lp[2];
#pragma unroll
        for (int q = 0; q < 2; q++) {
            float a0 = v[r * 4 + 2 * q], a1 = v[r * 4 + 2 * q + 1];
            __nv_bfloat16 h0 = __float2bfloat16(a0), h1 = __float2bfloat16(a1);
            __nv_bfloat16 l0 = __float2bfloat16(a0 - __bfloat162float(h0));
            __nv_bfloat16 l1 = __float2bfloat16(a1 - __bfloat162float(h1));
            hp[q] = (u32)__bfloat16_as_ushort(h0) | ((u32)__bfloat16_as_ushort(h1) << 16);
            lp[q] = (u32)__bfloat16_as_ushort(l0) | ((u32)__bfloat16_as_ushort(l1) << 16);
        }
        *(uint2*)&g_xt3h[(long)row * 512 + base] = make_uint2(hp[0], hp[1]);
        *(uint2*)&g_xt3l[(long)row * 512 + base] = make_uint2(lp[0], lp[1]);
    }
}

// -------- transpose + hi/lo split: X [b][ch][w] -> [b*2048+w][ch] ------------
__global__ void k_tcvt(const float* __restrict__ X,
                       __nv_bfloat16* __restrict__ Xh, __nv_bfloat16* __restrict__ Xl) {
    __shared__ float tile[32][33];
    int b = blockIdx.z, w0 = blockIdx.x * 32, c0 = blockIdx.y * 32;
    int tx = threadIdx.x, ty = threadIdx.y;   // 32 x 8
#pragma unroll
    for (int i = 0; i < 4; i++)
        tile[ty + i * 8][tx] = X[((long)b * 1024 + c0 + ty + i * 8) * 2048 + w0 + tx];
    __syncthreads();
#pragma unroll
    for (int i = 0; i < 4; i++) {
        float v = tile[tx][ty + i * 8];
        long o = ((long)(b * 2048 + w0 + ty + i * 8)) * 1024 + c0 + tx;
        __nv_bfloat16 h = __float2bfloat16(v);
        Xh[o] = h;
        Xl[o] = __float2bfloat16(v - __bfloat162float(h));
    }
}

// -------- weight repack: w[oc][ic][k] -> W[k][oc][ic] hi/lo ------------------
__global__ void k_wprep(const float* __restrict__ w,
                        __nv_bfloat16* __restrict__ Wh, __nv_bfloat16* __restrict__ Wl,
                        int OCt, int ICt) {
    long n = (long)OCt * ICt * 3;
    long i = (long)blockIdx.x * 256 + threadIdx.x;
    if (i >= n) return;
    int k = (int)(i / ((long)OCt * ICt));
    long rem = i - (long)k * OCt * ICt;
    int oc = (int)(rem / ICt), ic = (int)(rem % ICt);
    float v = w[((long)oc * ICt + ic) * 3 + k];
    __nv_bfloat16 h = __float2bfloat16(v);
    Wh[i] = h;
    Wl[i] = __float2bfloat16(v - __bfloat162float(h));
}

// -------- generic HMMA GEMM, bf16x3: C[m][n] = A[m][k] . B[n][k]^T ----------
// CTA 128x128, 8 warps 64x32. K-chunk 32, cp.async double buffer.
// EPI: 0 plain fp32 C; 2 hi/lo bf16 out scaled 1/sig2; 3 C = 2*aux + gm*acc
template <int EPI>
__global__ void __launch_bounds__(256) k_hgemm(
    const __nv_bfloat16* __restrict__ Ah, const __nv_bfloat16* __restrict__ Al,
    const __nv_bfloat16* __restrict__ Bh, const __nv_bfloat16* __restrict__ Bl,
    float* __restrict__ C, int M, int N, int K,
    long sA, long sB, long sC,
    __nv_bfloat16* __restrict__ Oh, __nv_bfloat16* __restrict__ Ol, long sO,
    const float* __restrict__ aux, long sAux, const float* __restrict__ gma) {
    extern __shared__ char dsm[];
    const int t = threadIdx.x, lane = t & 31, wid = t >> 5;
    const int bz = blockIdx.z;
    const int n0 = blockIdx.x * 128, m0 = blockIdx.y * 128;
    const int wm = wid >> 2, wn = wid & 3;
    const u32 smb = smem_u32(dsm);
    const int Cn = K >> 5;
    const char* Ahp = (const char*)Ah + (long)bz * sA * 2;
    const char* Alp = (const char*)Al + (long)bz * sA * 2;
    const char* Bhp = (const char*)Bh + (long)bz * sB * 2;
    const char* Blp = (const char*)Bl + (long)bz * sB * 2;

    float acc[4][4][4];
#pragma unroll
    for (int a = 0; a < 4; a++)
#pragma unroll
        for (int b = 0; b < 4; b++)
#pragma unroll
            for (int c = 0; c < 4; c++) acc[a][b][c] = 0.f;

    auto load_stage = [&](int c) {
        const u32 sb = smb + (u32)(c & 1) * 40960u;
#pragma unroll
        for (int i = 0; i < 2; i++) {
            int s = t + i * 256;
            int row = s >> 2, seg = (s & 3) << 4;
            long ga = (long)(m0 + row) * K * 2 + c * 64 + seg;
            u32 soA = sb + row * 80 + seg;
            cpasync(soA, Ahp + ga, 16u);
            cpasync(soA + 10240, Alp + ga, 16u);
            long gb = (long)(n0 + row) * K * 2 + c * 64 + seg;
            u32 soB = sb + 20480 + row * 80 + seg;
            cpasync(soB, Bhp + gb, 16u);
            cpasync(soB + 10240, Blp + gb, 16u);
        }
        CP_COMMIT();
    };

    load_stage(0);
    if (Cn > 1) load_stage(1);

    for (int c = 0; c < Cn; c++) {
        if (c + 1 < Cn) asm volatile("cp.async.wait_group 1;" ::: "memory");
        else            asm volatile("cp.async.wait_group 0;" ::: "memory");
        __syncthreads();
        const u32 sb = smb + (u32)(c & 1) * 40960u;
        const u32 aB = sb + (u32)(wm * 64 + (lane & 15)) * 80 + (u32)((lane >> 4) << 4);
        const u32 bB = sb + 20480u
                       + (u32)(wn * 32 + (lane & 7) + ((lane >> 4) << 3)) * 80
                       + (u32)(((lane >> 3) & 1) << 4);
#pragma unroll
        for (int ks = 0; ks < 2; ks++) {
            u32 AH[16], AL2[16], BH[8], BL[8];
#pragma unroll
            for (int mt = 0; mt < 4; mt++) {
                u32 a = aB + ks * 32 + mt * (16 * 80);
                LDM4(AH + mt * 4, a);
                LDM4(AL2 + mt * 4, a + 10240);
            }
#pragma unroll
            for (int np = 0; np < 2; np++) {
                u32 b = bB + ks * 32 + np * (16 * 80);
                LDM4(BH + np * 4, b);
                LDM4(BL + np * 4, b + 10240);
            }
#pragma unroll
            for (int mt = 0; mt < 4; mt++)
#pragma unroll
                for (int nt = 0; nt < 4; nt++) {
                    const int bi = (nt >> 1) * 4 + (nt & 1) * 2;
                    MMA(acc[mt][nt], AH + mt * 4, BH[bi], BH[bi + 1]);
                    MMA(acc[mt][nt], AH + mt * 4, BL[bi], BL[bi + 1]);
                    MMA(acc[mt][nt], AL2 + mt * 4, BH[bi], BH[bi + 1]);
                }
        }
        __syncthreads();
        if (c + 2 < Cn) load_stage(c + 2);
    }

    float sc = 1.f, gm = 0.f;
    if (EPI == 2) sc = 1.f / g_sig[2];
    else if (EPI == 3) gm = gma[0] / g_sig[3];

    const int mrb = wm * 64 + (lane >> 2);
#pragma unroll
    for (int mt = 0; mt < 4; mt++) {
        const int mr = m0 + mrb + mt * 16;
#pragma unroll
        for (int nt = 0; nt < 4; nt++) {
            const int nc = n0 + wn * 32 + nt * 8 + ((lane & 3) << 1);
            float v00 = acc[mt][nt][0], v01 = acc[mt][nt][1];
            float v10 = acc[mt][nt][2], v11 = acc[mt][nt][3];
            if (EPI == 0) {
                long off = (long)bz * sC + (long)mr * N + nc;
                *(float2*)(C + off) = make_float2(v00, v01);
                *(float2*)(C + off + (long)8 * N) = make_float2(v10, v11);
            } else if (EPI == 2) {
                v00 *= sc; v01 *= sc; v10 *= sc; v11 *= sc;
                __nv_bfloat16 h0 = __float2bfloat16(v00), h1 = __float2bfloat16(v01);
                __nv_bfloat16 h2 = __float2bfloat16(v10), h3 = __float2bfloat16(v11);
                u32 hp0 = (u32)__bfloat16_as_ushort(h0) | ((u32)__bfloat16_as_ushort(h1) << 16);
                u32 hp1 = (u32)__bfloat16_as_ushort(h2) | ((u32)__bfloat16_as_ushort(h3) << 16);
                __nv_bfloat16 l0 = __float2bfloat16(v00 - __bfloat162float(h0));
                __nv_bfloat16 l1 = __float2bfloat16(v01 - __bfloat162float(h1));
                __nv_bfloat16 l2 = __float2bfloat16(v10 - __bfloat162float(h2));
                __nv_bfloat16 l3 = __float2bfloat16(v11 - __bfloat162float(h3));
                u32 lp0 = (u32)__bfloat16_as_ushort(l0) | ((u32)__bfloat16_as_ushort(l1) << 16);
                u32 lp1 = (u32)__bfloat16_as_ushort(l2) | ((u32)__bfloat16_as_ushort(l3) << 16);
                long off = (long)bz * sO + (long)mr * N + nc;
                *(u32*)(Oh + off) = hp0;
                *(u32*)(Oh + off + (long)8 * N) = hp1;
                *(u32*)(Ol + off) = lp0;
                *(u32*)(Ol + off + (long)8 * N) = lp1;
            } else {
                long off = (long)bz * sC + (long)mr * N + nc;
                float2 a0 = *(const float2*)(aux + (long)bz * sAux + (long)mr * N + nc);
                float2 a1 = *(const float2*)(aux + (long)bz * sAux + (long)(mr + 8) * N + nc);
                *(float2*)(C + off) =
                    make_float2(2.f * a0.x + gm * v00, 2.f * a0.y + gm * v01);
                *(float2*)(C + off + (long)8 * N) =
                    make_float2(2.f * a1.x + gm * v10, 2.f * a1.y + gm * v11);
            }
        }
    }
}

// -------- conv1d k=3 'same' via mma.sync HMMA, bf16x3 split (unchanged) ------
template <int FINAL>
__global__ void __launch_bounds__(256) k_convhmma(
    const __nv_bfloat16* __restrict__ Xh, const __nv_bfloat16* __restrict__ Xl,
    const __nv_bfloat16* __restrict__ Wh, const __nv_bfloat16* __restrict__ Wl,
    const float* __restrict__ bias, int IC, int OCt,
    __nv_bfloat16* __restrict__ Yh, __nv_bfloat16* __restrict__ Yl,
    float* __restrict__ Yt) {
    extern __shared__ char dsm[];
    const int t = threadIdx.x, lane = t & 31, wid = t >> 5;
    const int oc0 = blockIdx.x * 128;
    const int Mtile = blockIdx.y;
    const int bb = Mtile >> 4, w0 = (Mtile & 15) << 7;
    const int wm = wid >> 2, wn = wid & 3;
    const u32 smb = smem_u32(dsm);
    const int nic = IC >> 5;
    const int C = 3 * nic;

    float acc[4][4][4];
#pragma unroll
    for (int a = 0; a < 4; a++)
#pragma unroll
        for (int b = 0; b < 4; b++)
#pragma unroll
            for (int c = 0; c < 4; c++) acc[a][b][c] = 0.f;

    auto load_stage = [&](int c) {
        const int kshift = c / nic;
        const int icc = (c - kshift * nic) << 5;
        const u32 sb = smb + (u32)(c & 1) * 40960u;
#pragma unroll
        for (int i = 0; i < 2; i++) {
            int s = t + i * 256;
            int row = s >> 2, segc = (s & 3) << 4;
            int wl = w0 + row + kshift - 1;
            u32 ok = (wl >= 0 && wl < 2048) ? 16u : 0u;
            int wcl = wl < 0 ? 0 : (wl > 2047 ? 2047 : wl);
            long ga = ((long)(bb * 2048 + wcl) * IC + icc) * 2 + segc;
            u32 soA = sb + row * 80 + segc;
            cpasync(soA, (const char*)Xh + ga, ok);
            cpasync(soA + 10240, (const char*)Xl + ga, ok);
            long gb = ((long)(kshift * OCt + oc0 + row) * IC + icc) * 2 + segc;
            u32 soB = sb + 20480 + row * 80 + segc;
            cpasync(soB, (const char*)Wh + gb, 16u);
            cpasync(soB + 10240, (const char*)Wl + gb, 16u);
        }
        CP_COMMIT();
    };

    load_stage(0);
    if (C > 1) load_stage(1);

    for (int c = 0; c < C; c++) {
        if (c + 1 < C) asm volatile("cp.async.wait_group 1;" ::: "memory");
        else           asm volatile("cp.async.wait_group 0;" ::: "memory");
        __syncthreads();
        const u32 sb = smb + (u32)(c & 1) * 40960u;
        const u32 aB = sb + (u32)(wm * 64 + (lane & 15)) * 80 + (u32)((lane >> 4) << 4);
        const u32 bB = sb + 20480u
                       + (u32)(wn * 32 + (lane & 7) + ((lane >> 4) << 3)) * 80
                       + (u32)(((lane >> 3) & 1) << 4);
#pragma unroll
        for (int ks = 0; ks < 2; ks++) {
            u32 AH[16], AL2[16], BH[8], BL[8];
#pragma unroll
            for (int mt = 0; mt < 4; mt++) {
                u32 a = aB + ks * 32 + mt * (16 * 80);
                LDM4(AH + mt * 4, a);
                LDM4(AL2 + mt * 4, a + 10240);
            }
#pragma unroll
            for (int np = 0; np < 2; np++) {
                u32 b = bB + ks * 32 + np * (16 * 80);
                LDM4(BH + np * 4, b);
                LDM4(BL + np * 4, b + 10240);
            }
#pragma unroll
            for (int mt = 0; mt < 4; mt++)
#pragma unroll
                for (int nt = 0; nt < 4; nt++) {
                    const int bi = (nt >> 1) * 4 + (nt & 1) * 2;
                    MMA(acc[mt][nt], AH + mt * 4, BH[bi], BH[bi + 1]);
                    MMA(acc[mt][nt], AH + mt * 4, BL[bi], BL[bi + 1]);
                    MMA(acc[mt][nt], AL2 + mt * 4, BH[bi], BH[bi + 1]);
                }
        }
        __syncthreads();
        if (c + 2 < C) load_stage(c + 2);
    }

    const int mrb = wm * 64 + (lane >> 2);
#pragma unroll
    for (int mt = 0; mt < 4; mt++) {
        const int mr = mrb + mt * 16;
        const long grow = (long)Mtile * 128 + mr;
#pragma unroll
        for (int nt = 0; nt < 4; nt++) {
            const int oc = oc0 + wn * 32 + nt * 8 + ((lane & 3) << 1);
            const float b0v = __ldg(bias + oc), b1v = __ldg(bias + oc + 1);
            float v00 = fmaxf(acc[mt][nt][0] + b0v, 0.f);
            float v01 = fmaxf(acc[mt][nt][1] + b1v, 0.f);
            float v10 = fmaxf(acc[mt][nt][2] + b0v, 0.f);
            float v11 = fmaxf(acc[mt][nt][3] + b1v, 0.f);
            if (FINAL) {
                *(float2*)(Yt + grow * OCt + oc) = make_float2(v00, v01);
                *(float2*)(Yt + (grow + 8) * OCt + oc) = make_float2(v10, v11);
            } else {
                __nv_bfloat16 h0 = __float2bfloat16(v00);
                __nv_bfloat16 h1 = __float2bfloat16(v01);
                __nv_bfloat16 h2 = __float2bfloat16(v10);
                __nv_bfloat16 h3 = __float2bfloat16(v11);
                u32 hp0 = (u32)__bfloat16_as_ushort(h0) |
                          ((u32)__bfloat16_as_ushort(h1) << 16);
                u32 hp1 = (u32)__bfloat16_as_ushort(h2) |
                          ((u32)__bfloat16_as_ushort(h3) << 16);
                __nv_bfloat16 l0 = __float2bfloat16(v00 - __bfloat162float(h0));
                __nv_bfloat16 l1 = __float2bfloat16(v01 - __bfloat162float(h1));
                __nv_bfloat16 l2 = __float2bfloat16(v10 - __bfloat162float(h2));
                __nv_bfloat16 l3 = __float2bfloat16(v11 - __bfloat162float(h3));
                u32 lp0 = (u32)__bfloat16_as_ushort(l0) |
                          ((u32)__bfloat16_as_ushort(l1) << 16);
                u32 lp1 = (u32)__bfloat16_as_ushort(l2) |
                          ((u32)__bfloat16_as_ushort(l3) << 16);
                *(u32*)(Yh + grow * OCt + oc) = hp0;
                *(u32*)(Yh + (grow + 8) * OCt + oc) = hp1;
                *(u32*)(Yl + grow * OCt + oc) = lp0;
                *(u32*)(Yl + (grow + 8) * OCt + oc) = lp1;
            }
        }
    }
}

// -------- final transpose + residual: out[b][oc][w] = T[b*2048+w][oc]+src ----
__global__ void k_fin(const float* __restrict__ T, const float* __restrict__ src,
                      float* __restrict__ out) {
    __shared__ float tile[32][33];
    int b = blockIdx.z, w0 = blockIdx.x * 32, c0 = blockIdx.y * 32;
    int tx = threadIdx.x, ty = threadIdx.y;   // 32 x 8
#pragma unroll
    for (int i = 0; i < 4; i++)
        tile[ty + i * 8][tx] = T[((long)(b * 2048 + w0 + ty + i * 8)) * 1024 + c0 + tx];
    __syncthreads();
#pragma unroll
    for (int i = 0; i < 4; i++) {
        long o = ((long)(b * 1024 + c0 + ty + i * 8)) * 2048 + w0 + tx;
        out[o] = tile[tx][ty + i * 8] + src[o];
    }
}

// ---------------- launch ----------------
extern "C" void kernel_launch(void* const* d_in, const int* in_sizes, int n_in,
                              void* d_out, int out_size) {
    const float* src     = (const float*)d_in[0];
    const float* w_theta = (const float*)d_in[1];
    const float* w_phi   = (const float*)d_in[2];
    const float* w_g     = (const float*)d_in[3];
    const float* w_o     = (const float*)d_in[4];
    const float* gamma   = (const float*)d_in[5];
    const float* w_c1 = (const float*)d_in[6];  const float* b_c1 = (const float*)d_in[7];
    const float* w_c2 = (const float*)d_in[8];  const float* b_c2 = (const float*)d_in[9];
    const float* w_c3 = (const float*)d_in[10]; const float* b_c3 = (const float*)d_in[11];
    const float* w_c4 = (const float*)d_in[12]; const float* b_c4 = (const float*)d_in[13];
    float* out = (float*)d_out;

    static float *p_proj = nullptr, *p_phir, *p_attn, *p_x, *p_gram;
    static __nv_bfloat16 *x1h, *x1l, *x2h, *x2l, *x3h, *x3l, *x4h, *x4l;
    static __nv_bfloat16 *w1h, *w1l, *w2h, *w2l, *w3h, *w3l, *w4h, *w4l;
    if (!p_proj) {
        cudaGetSymbolAddress((void**)&p_proj,  g_proj);
        cudaGetSymbolAddress((void**)&p_phir,  g_phir);
        cudaGetSymbolAddress((void**)&p_attn,  g_attn);
        cudaGetSymbolAddress((void**)&p_x,     g_x);
        cudaGetSymbolAddress((void**)&p_gram,  g_gram);
        cudaGetSymbolAddress((void**)&x1h, g_xt1h); cudaGetSymbolAddress((void**)&x1l, g_xt1l);
        cudaGetSymbolAddress((void**)&x2h, g_xt2h); cudaGetSymbolAddress((void**)&x2l, g_xt2l);
        cudaGetSymbolAddress((void**)&x3h, g_xt3h); cudaGetSymbolAddress((void**)&x3l, g_xt3l);
        cudaGetSymbolAddress((void**)&x4h, g_xt4h); cudaGetSymbolAddress((void**)&x4l, g_xt4l);
        cudaGetSymbolAddress((void**)&w1h, g_w1h);  cudaGetSymbolAddress((void**)&w1l, g_w1l);
        cudaGetSymbolAddress((void**)&w2h, g_w2h);  cudaGetSymbolAddress((void**)&w2l, g_w2l);
        cudaGetSymbolAddress((void**)&w3h, g_w3h);  cudaGetSymbolAddress((void**)&w3l, g_w3l);
        cudaGetSymbolAddress((void**)&w4h, g_w4h);  cudaGetSymbolAddress((void**)&w4l, g_w4l);
        cudaFuncSetAttribute(k_convhmma<0>,
                             cudaFuncAttributeMaxDynamicSharedMemorySize, 81920);
        cudaFuncSetAttribute(k_convhmma<1>,
                             cudaFuncAttributeMaxDynamicSharedMemorySize, 81920);
        cudaFuncSetAttribute(k_hgemm<0>,
                             cudaFuncAttributeMaxDynamicSharedMemorySize, 81920);
        cudaFuncSetAttribute(k_hgemm<2>,
                             cudaFuncAttributeMaxDynamicSharedMemorySize, 81920);
        cudaFuncSetAttribute(k_hgemm<3>,
                             cudaFuncAttributeMaxDynamicSharedMemorySize, 81920);
    }

    // 1) projections on HMMA: proj[b][768][2048] = Wpack . srcT^T
    k_packsplit<<<3072, 256>>>(w_theta, w_phi, w_g);       // -> w1h/w1l
    k_tcvt<<<dim3(64, 32, 4), dim3(32, 8)>>>(src, x1h, x1l);   // srcT hi/lo
    k_wosplit<<<2048, 256>>>(w_o);                         // -> w2h/w2l
    k_hgemm<0><<<dim3(16, 6, 4), 256, 81920>>>(w1h, w1l, x1h, x1l, p_proj,
        768, 2048, 1024, 0, 2097152, 1572864, nullptr, nullptr, 0, nullptr, 0, nullptr);
    // 2) pools: phir fp32; g_r -> hi/lo (x2h/x2l)
    k_pool<<<1024, 256>>>(0);
    k_pool<<<4096, 256>>>(1);
    // 3) Gram matrices (SIMT, fp32-exact)
    k_gemm<0, 1, 0><<<dim3(2, 1, 1), 256>>>(w_theta, w_theta, p_gram,
        128, 128, 1024, 0, 0, 0, nullptr, 0, nullptr);
    k_gemm<0, 1, 0><<<dim3(2, 1, 1), 256>>>(w_phi, w_phi, p_gram + 262144,
        128, 128, 1024, 0, 0, 0, nullptr, 0, nullptr);
    k_gemm<0, 1, 0><<<dim3(8, 4, 1), 256>>>(w_g, w_g, p_gram + 524288,
        512, 512, 1024, 0, 0, 0, nullptr, 0, nullptr);
    k_gemm<1, 0, 0><<<dim3(8, 4, 1), 256>>>(w_o, w_o, p_gram + 786432,
        512, 512, 1024, 0, 0, 0, nullptr, 0, nullptr);
    // 4) sigma chain
    k_trace<<<4, 512>>>(0, 0);
    for (int s = 1; s <= 10; s++) {
        k_sq<<<dim3(2, 1, 2), 256>>>((s - 1) & 1, s, 0);
        k_sq<<<dim3(8, 4, 2), 256>>>((s - 1) & 1, s, 1);
        k_trace<<<4, 512>>>(s, s & 1);
    }
    k_sigfinal<<<1, 4>>>(10);
    // 5) logits (SIMT, K=128 small) + softmax (emits hi/lo -> x3h/x3l)
    k_gemm<1, 0, 1><<<dim3(8, 16, 4), 256>>>(p_proj, p_phir, p_attn,
        2048, 512, 128, 1572864, 65536, 1048576, nullptr, 0, nullptr);
    k_softmax<<<1024, 256>>>();
    // 6) attn_g^T on HMMA: agT[w][c] = attn[w][v] . g_r[c][v]^T, *1/sig_g -> x4h/x4l
    k_hgemm<2><<<dim3(4, 16, 4), 256, 81920>>>(x3h, x3l, x2h, x2l, nullptr,
        2048, 512, 512, 1048576, 262144, 0, x4h, x4l, 1048576, nullptr, 0, nullptr);
    // 7) x = 2*src + (gamma/sig_o) * (w_o . agT^T) on HMMA -> g_x [b][ch][w]
    k_hgemm<3><<<dim3(16, 8, 4), 256, 81920>>>(w2h, w2l, x4h, x4l, p_x,
        1024, 2048, 512, 0, 1048576, 2097152, nullptr, nullptr, 0,
        src, 2097152, gamma);
    // 8) conv FFN on HMMA (unchanged; buffers reused after their readers)
    k_tcvt<<<dim3(64, 32, 4), dim3(32, 8)>>>(p_x, x1h, x1l);
    k_wprep<<<6144, 256>>>(w_c1, w1h, w1l, 512, 1024);
    k_wprep<<<3072, 256>>>(w_c2, w2h, w2l, 512, 512);
    k_wprep<<<3072, 256>>>(w_c3, w3h, w3l, 512, 512);
    k_wprep<<<6144, 256>>>(w_c4, w4h, w4l, 1024, 512);
    k_convhmma<0><<<dim3(4, 64), 256, 81920>>>(x1h, x1l, w1h, w1l, b_c1,
        1024, 512, x2h, x2l, nullptr);
    k_convhmma<0><<<dim3(4, 64), 256, 81920>>>(x2h, x2l, w2h, w2l, b_c2,
        512, 512, x3h, x3l, nullptr);
    k_convhmma<0><<<dim3(4, 64), 256, 81920>>>(x3h, x3l, w3h, w3l, b_c3,
        512, 512, x4h, x4l, nullptr);
    k_convhmma<1><<<dim3(8, 64), 256, 81920>>>(x4h, x4l, w4h, w4l, b_c4,
        512, 1024, nullptr, nullptr, p_x);
    k_fin<<<dim3(64, 32, 4), dim3(32, 8)>>>(p_x, src, out);
    (void)in_sizes; (void)n_in; (void)out_size;
}